// round 14
// baseline (speedup 1.0000x reference)
#include <cuda_runtime.h>
#include <cuda_fp16.h>
#include <math.h>
#include <stddef.h>
#include <stdint.h>

// ---------------- problem constants ----------------
constexpr int BB   = 8;
constexpr int TT   = 16;
constexpr int NN   = 256;
constexpr int CB   = 1024;
constexpr int HH   = 16;
constexpr int HDD  = 64;
constexpr int KEXP = 8;
constexpr int BTT  = BB * TT;          // 128
constexpr int MROWS = BTT * NN;        // 32768
constexpr float EPS = 1e-5f;
constexpr size_t QK  = (size_t)MROWS * CB;
constexpr size_t WNS = (size_t)CB * CB;

// ---------------- device scratch ----------------
__device__ __align__(128) float g_qsum[KEXP * CB];
__device__ __align__(128) float g_ksum[KEXP * CB];
__device__ __align__(128) float g_dyn[BB * NN * KEXP];
__device__ __align__(128) float g_bc[CB];

__device__ __align__(128) __half g_xh  [QK];
__device__ __align__(128) __half g_qkh [2 * QK];
__device__ __align__(128) __half g_qkl [2 * QK];
__device__ __align__(128) __half g_qpkh[2 * QK];
__device__ __align__(128) __half g_qpkl[2 * QK];
__device__ __align__(128) __half g_vpth[QK];
__device__ __align__(128) __half g_cxh [QK];

__device__ __align__(128) __half w_qkh [2 * WNS];
__device__ __align__(128) __half w_qkl [2 * WNS];
__device__ __align__(128) __half w_wvh [WNS];
__device__ __align__(128) __half w_wvl [WNS];
__device__ __align__(128) __half w_vwth[WNS];
__device__ __align__(128) __half w_vwtl[WNS];
__device__ __align__(128) __half w_wch [WNS];
__device__ __align__(128) __half w_owh [WNS];

// ---------------- helpers ----------------
__device__ __forceinline__ uint32_t smem_u32(const void* p) {
    return (uint32_t)__cvta_generic_to_shared(p);
}
__device__ __forceinline__ uint32_t sw128(uint32_t o) { return o ^ ((o >> 3) & 0x70); }
__device__ __forceinline__ float hfr(float a) { return __half2float(__float2half_rn(a)); }
__device__ __forceinline__ uint32_t packh2(float a, float b) {
    __half2 t = __floats2half2_rn(a, b);
    return *(uint32_t*)&t;
}
__device__ __forceinline__ void ldsm_x4(uint32_t& r0, uint32_t& r1, uint32_t& r2, uint32_t& r3,
                                        uint32_t addr) {
    asm volatile("ldmatrix.sync.aligned.m8n8.x4.shared.b16 {%0,%1,%2,%3}, [%4];"
                 : "=r"(r0), "=r"(r1), "=r"(r2), "=r"(r3) : "r"(addr));
}
__device__ __forceinline__ void mma16816(float* d, const uint32_t* a, uint32_t b0, uint32_t b1) {
    asm volatile("mma.sync.aligned.m16n8k16.row.col.f32.f16.f16.f32 "
                 "{%0,%1,%2,%3}, {%4,%5,%6,%7}, {%8,%9}, {%0,%1,%2,%3};"
                 : "+f"(d[0]), "+f"(d[1]), "+f"(d[2]), "+f"(d[3])
                 : "r"(a[0]), "r"(a[1]), "r"(a[2]), "r"(a[3]), "r"(b0), "r"(b1));
}
__device__ __forceinline__ void cp16(uint32_t dst, const void* src) {
    asm volatile("cp.async.cg.shared.global [%0], [%1], 16;" :: "r"(dst), "l"(src) : "memory");
}
__device__ __forceinline__ void cp_commit() { asm volatile("cp.async.commit_group;" ::: "memory"); }
template<int N> __device__ __forceinline__ void cp_wait() {
    asm volatile("cp.async.wait_group %0;" :: "n"(N) : "memory");
}

// ---------------- fp16 split HMMA GEMM, multi-stage cp.async pipeline ----------------
// Template: NPROD products, OMODE, BN (128 or 256), NSTAGE.
// THREADS = 512 for BN=256 (16 warps, 4x4), else 256 (8 warps, 4x2). Warp tile 32x64.
// NPROD=3: (A0+A1)@(B0+B1) via hh,hl,lh.  NPROD=1: A0@B0.
// OMODE 0: row-major out (Cf fp32 / Ch+Cl split2 / Ch single), bias per COL, optional resid,
//          gridDim.z batching (az: A,C stride; bz: B stride; bias += z*CB).
// OMODE 2: vpT write — out[col>>8][row][col&255] half, bias per ROW.
template<int NPROD, int OMODE, int BN, int NSTAGE>
__global__ void __launch_bounds__((BN == 256) ? 512 : 256, (NPROD == 1) ? 2 : 1)
hmma_f16(const __half* __restrict__ A0, const __half* __restrict__ A1,
         const __half* __restrict__ B0, const __half* __restrict__ B1,
         float* __restrict__ Cf, __half* __restrict__ Ch, __half* __restrict__ Cl,
         int Kdim, int lda, int ldb, int ldc,
         const float* __restrict__ bias, const float* __restrict__ resid,
         size_t az, size_t bz)
{
    constexpr int THREADS = (BN == 256) ? 512 : 256;
    constexpr int NSA   = (NPROD >= 2) ? 2 : 1;
    constexpr int NSB   = (NPROD == 3) ? 2 : 1;
    constexpr int ATILE = 128 * 64 * 2;
    constexpr int BTILE = BN * 64 * 2;
    constexpr int STAGE = NSA * ATILE + NSB * BTILE;
    constexpr int A16   = ATILE / 16;
    constexpr int B16   = BTILE / 16;

    extern __shared__ char dsm[];
    const uint32_t sraw  = smem_u32(dsm);
    const uint32_t sbase = (sraw + 127u) & ~127u;

    const int tid  = threadIdx.x;
    const int wid  = tid >> 5;
    const int lane = tid & 31;
    const int wm   = wid & 3;
    const int wn   = wid >> 2;

    if (OMODE == 0 && blockIdx.z) {
        size_t zo = blockIdx.z * az, zb = blockIdx.z * bz;
        A0 += zo; if (A1) A1 += zo;
        B0 += zb; if (B1) B1 += zb;
        if (Cf) Cf += zo;
        if (Ch) { Ch += zo; if (Cl) Cl += zo; }
        if (bias) bias += blockIdx.z * CB;
    }

    const __half* Ap[2] = {A0, A1};
    const __half* Bp[2] = {B0, B1};
    const int bm = blockIdx.y * 128, bn = blockIdx.x * BN;

    auto issue = [&](int s, int kt) {
        uint32_t st = sbase + s * STAGE;
        #pragma unroll
        for (int p = 0; p < NSA; p++) {
            const __half* As = Ap[p];
            #pragma unroll
            for (int r = 0; r < A16 / THREADS; r++) {
                int i = tid + r * THREADS;
                int row = i >> 3, ch = (i & 7) * 16;
                cp16(st + p * ATILE + sw128((uint32_t)(row * 128 + ch)),
                     (const char*)(As + (size_t)(bm + row) * lda + kt) + ch);
            }
        }
        #pragma unroll
        for (int p = 0; p < NSB; p++) {
            const __half* Bs = Bp[p];
            #pragma unroll
            for (int r = 0; r < B16 / THREADS; r++) {
                int i = tid + r * THREADS;
                int row = i >> 3, ch = (i & 7) * 16;
                cp16(st + NSA * ATILE + p * BTILE + sw128((uint32_t)(row * 128 + ch)),
                     (const char*)(Bs + (size_t)(bn + row) * ldb + kt) + ch);
            }
        }
        cp_commit();
    };

    float acc[2][8][4];
    #pragma unroll
    for (int mt = 0; mt < 2; mt++)
        #pragma unroll
        for (int nt = 0; nt < 8; nt++)
            #pragma unroll
            for (int j = 0; j < 4; j++) acc[mt][nt][j] = 0.f;

    const uint32_t a_roff = (uint32_t)((wm * 32 + (lane & 15)) * 128 + ((lane >> 4) << 4));
    const uint32_t b_roff = (uint32_t)((wn * 64 + ((lane >> 4) << 3) + (lane & 7)) * 128
                                       + (((lane >> 3) & 1) << 4));

    auto compute = [&](int s) {
        uint32_t st = sbase + s * STAGE;
        #pragma unroll
        for (int p = 0; p < NPROD; p++) {
            int pa, pb;
            if (NPROD == 3)      { pa = (p == 2) ? 1 : 0; pb = (p == 1) ? 1 : 0; }
            else                 { pa = 0; pb = 0; }
            uint32_t abp = st + pa * ATILE;
            uint32_t bbp = st + NSA * ATILE + pb * BTILE;
            #pragma unroll
            for (int ks = 0; ks < 4; ks++) {
                uint32_t a[2][4];
                #pragma unroll
                for (int mt = 0; mt < 2; mt++)
                    ldsm_x4(a[mt][0], a[mt][1], a[mt][2], a[mt][3],
                            abp + sw128(a_roff + mt * 16 * 128 + ks * 32));
                #pragma unroll
                for (int bp = 0; bp < 4; bp++) {
                    uint32_t b0, b1, b2, b3;
                    ldsm_x4(b0, b1, b2, b3, bbp + sw128(b_roff + bp * 16 * 128 + ks * 32));
                    #pragma unroll
                    for (int mt = 0; mt < 2; mt++) {
                        mma16816(acc[mt][2 * bp],     a[mt], b0, b1);
                        mma16816(acc[mt][2 * bp + 1], a[mt], b2, b3);
                    }
                }
            }
        }
    };

    const int nch = Kdim / 64;
    #pragma unroll
    for (int s = 0; s < NSTAGE; s++)
        if (s < nch) issue(s, s * 64);
    for (int t = 0; t < nch; t++) {
        int rem = nch - 1 - t;
        if (NSTAGE == 3) {
            if (rem >= 2) cp_wait<2>();
            else if (rem == 1) cp_wait<1>();
            else cp_wait<0>();
        } else {
            if (rem >= 1) cp_wait<1>();
            else cp_wait<0>();
        }
        __syncthreads();
        compute(t % NSTAGE);
        __syncthreads();
        if (t + NSTAGE < nch) issue(t % NSTAGE, (t + NSTAGE) * 64);
    }

    // ---- epilogue ----
    #pragma unroll
    for (int mt = 0; mt < 2; mt++) {
        int r0 = bm + wm * 32 + mt * 16 + (lane >> 2);
        #pragma unroll
        for (int nt = 0; nt < 8; nt++) {
            int col = bn + wn * 64 + nt * 8 + (lane & 3) * 2;
            #pragma unroll
            for (int rr = 0; rr < 2; rr++) {
                int row = r0 + rr * 8;
                float v0 = acc[mt][nt][2 * rr];
                float v1 = acc[mt][nt][2 * rr + 1];
                if (OMODE == 2) {
                    float b = bias[row];
                    v0 += b; v1 += b;
                    size_t t0 = (size_t)(col >> 8) * (CB * NN) + (size_t)row * NN + (col & 255);
                    *(__half2*)(Ch + t0) = __floats2half2_rn(v0, v1);
                } else {
                    if (bias)  { v0 += bias[col]; v1 += bias[col + 1]; }
                    if (resid) {
                        const float* rp = resid + (size_t)row * ldc + col;
                        v0 += rp[0]; v1 += rp[1];
                    }
                    size_t base = (size_t)row * ldc + col;
                    if (Cf) *(float2*)(Cf + base) = make_float2(v0, v1);
                    if (Ch && Cl) {
                        float h0 = hfr(v0), h1 = hfr(v1);
                        *(__half2*)(Ch + base) = __floats2half2_rn(h0, h1);
                        *(__half2*)(Cl + base) = __floats2half2_rn(v0 - h0, v1 - h1);
                    } else if (Ch) {
                        *(__half2*)(Ch + base) = __floats2half2_rn(v0, v1);
                    }
                }
            }
        }
    }
}

// ---------------- flash attention (staged loads, fused attn_avg, NP1 PV) ----------------
__global__ void __launch_bounds__(256)
flash_kernel(const __half* __restrict__ qph, const __half* __restrict__ qpl,
             const __half* __restrict__ kph, const __half* __restrict__ kpl,
             const __half* __restrict__ vpt,
             float* __restrict__ out2, __half* __restrict__ cxh)
{
    extern __shared__ char dsm[];
    const uint32_t sraw = smem_u32(dsm);
    const uint32_t sb   = (sraw + 127u) & ~127u;
    char* const ab      = dsm + (sb - sraw);

    const int tid = threadIdx.x, wid = tid >> 5, lane = tid & 31;
    const int wm = wid & 3, wn = wid >> 2;
    const int z = blockIdx.y;
    const int bt = z >> 4, head = z & 15;
    const int bm = blockIdx.x * 128;

    const size_t qoff = (size_t)bt * NN * CB + (size_t)head * HDD;
    const size_t voff = (size_t)bt * CB * NN + (size_t)head * HDD * NN;

    {
        const __half* qs[2] = {qph, qpl};
        #pragma unroll
        for (int p = 0; p < 2; p++)
            #pragma unroll
            for (int r = 0; r < 4; r++) {
                int i = tid + r * 256;
                int row = i >> 3, ch = (i & 7) * 16;
                cp16(sb + p * 16384 + sw128((uint32_t)(row * 128 + ch)),
                     (const char*)(qs[p] + qoff + (size_t)(bm + row) * CB) + ch);
            }
        #pragma unroll
        for (int r = 0; r < 8; r++) {
            int i = tid + r * 256;
            int row = i >> 3, ch = (i & 7) * 16;
            cp16(sb + 32768 + sw128((uint32_t)(row * 128 + ch)),
                 (const char*)(kph + qoff + (size_t)row * CB) + ch);
        }
        cp_commit();
        #pragma unroll
        for (int r = 0; r < 8; r++) {
            int i = tid + r * 256;
            int row = i >> 3, ch = (i & 7) * 16;
            cp16(sb + 65536 + sw128((uint32_t)(row * 128 + ch)),
                 (const char*)(kpl + qoff + (size_t)row * CB) + ch);
        }
        cp_commit();
        #pragma unroll
        for (int c = 0; c < 4; c++)
            #pragma unroll
            for (int r = 0; r < 2; r++) {
                int i = tid + r * 256;
                int row = i >> 3, ch = (i & 7) * 16;
                cp16(sb + 98304 + c * 8192 + sw128((uint32_t)(row * 128 + ch)),
                     (const char*)(vpt + voff + (size_t)row * NN + c * 64) + ch);
            }
        cp_commit();
        cp_wait<2>();
        __syncthreads();
    }

    float accS[2][16][4];
    #pragma unroll
    for (int mt = 0; mt < 2; mt++)
        #pragma unroll
        for (int nt = 0; nt < 16; nt++)
            #pragma unroll
            for (int j = 0; j < 4; j++) accS[mt][nt][j] = 0.f;

    const uint32_t a_roff = (uint32_t)((wm * 32 + (lane & 15)) * 128 + ((lane >> 4) << 4));
    const uint32_t b_roff = (uint32_t)((wn * 128 + ((lane >> 4) << 3) + (lane & 7)) * 128
                                       + (((lane >> 3) & 1) << 4));
    #pragma unroll
    for (int p = 0; p < 3; p++) {
        if (p == 2) { cp_wait<1>(); __syncthreads(); }
        uint32_t abp = sb + ((p == 1) ? 16384u : 0u);
        uint32_t bbp = sb + ((p == 2) ? 65536u : 32768u);
        #pragma unroll
        for (int ks = 0; ks < 4; ks++) {
            uint32_t a[2][4];
            #pragma unroll
            for (int mt = 0; mt < 2; mt++)
                ldsm_x4(a[mt][0], a[mt][1], a[mt][2], a[mt][3],
                        abp + sw128(a_roff + mt * 16 * 128 + ks * 32));
            #pragma unroll
            for (int bp = 0; bp < 8; bp++) {
                uint32_t b0, b1, b2, b3;
                ldsm_x4(b0, b1, b2, b3, bbp + sw128(b_roff + bp * 16 * 128 + ks * 32));
                #pragma unroll
                for (int mt = 0; mt < 2; mt++) {
                    mma16816(accS[mt][2 * bp],     a[mt], b0, b1);
                    mma16816(accS[mt][2 * bp + 1], a[mt], b2, b3);
                }
            }
        }
    }
    __syncthreads();

    float* red = (float*)ab;
    float rmax[2][2];
    #pragma unroll
    for (int mt = 0; mt < 2; mt++)
        #pragma unroll
        for (int rr = 0; rr < 2; rr++) {
            float m = -1e30f;
            #pragma unroll
            for (int nt = 0; nt < 16; nt++)
                m = fmaxf(m, fmaxf(accS[mt][nt][2 * rr], accS[mt][nt][2 * rr + 1]));
            m = fmaxf(m, __shfl_xor_sync(0xffffffffu, m, 1));
            m = fmaxf(m, __shfl_xor_sync(0xffffffffu, m, 2));
            int rowl = wm * 32 + mt * 16 + rr * 8 + (lane >> 2);
            if ((lane & 3) == 0) red[wn * 128 + rowl] = m;
        }
    __syncthreads();
    #pragma unroll
    for (int mt = 0; mt < 2; mt++)
        #pragma unroll
        for (int rr = 0; rr < 2; rr++) {
            int rowl = wm * 32 + mt * 16 + rr * 8 + (lane >> 2);
            rmax[mt][rr] = fmaxf(red[rowl], red[128 + rowl]);
        }
    __syncthreads();
    #pragma unroll
    for (int mt = 0; mt < 2; mt++)
        #pragma unroll
        for (int rr = 0; rr < 2; rr++) {
            float m = rmax[mt][rr], s = 0.f;
            #pragma unroll
            for (int nt = 0; nt < 16; nt++) {
                float e0 = __expf((accS[mt][nt][2 * rr]     - m) * 0.125f);
                float e1 = __expf((accS[mt][nt][2 * rr + 1] - m) * 0.125f);
                accS[mt][nt][2 * rr]     = e0;
                accS[mt][nt][2 * rr + 1] = e1;
                s += e0 + e1;
            }
            s += __shfl_xor_sync(0xffffffffu, s, 1);
            s += __shfl_xor_sync(0xffffffffu, s, 2);
            int rowl = wm * 32 + mt * 16 + rr * 8 + (lane >> 2);
            if ((lane & 3) == 0) red[wn * 128 + rowl] = s;
        }
    __syncthreads();

    #pragma unroll
    for (int mt = 0; mt < 2; mt++)
        #pragma unroll
        for (int rr = 0; rr < 2; rr++) {
            int rowl = wm * 32 + mt * 16 + rr * 8 + (lane >> 2);
            float inv = 1.f / (red[rowl] + red[128 + rowl]);
            float* orow = out2 + (size_t)bt * (NN * NN) + (size_t)(bm + rowl) * NN
                        + wn * 128 + (lane & 3) * 2;
            #pragma unroll
            for (int nt = 0; nt < 16; nt++) {
                float p0 = accS[mt][nt][2 * rr]     * inv;
                float p1 = accS[mt][nt][2 * rr + 1] * inv;
                accS[mt][nt][2 * rr]     = p0;
                accS[mt][nt][2 * rr + 1] = p1;
                atomicAdd(orow + nt * 8,     p0 * (1.f / HH));
                atomicAdd(orow + nt * 8 + 1, p1 * (1.f / HH));
            }
        }

    cp_wait<0>();
    __syncthreads();

    float accPV[2][8][4];
    #pragma unroll
    for (int mt = 0; mt < 2; mt++)
        #pragma unroll
        for (int nt = 0; nt < 8; nt++)
            #pragma unroll
            for (int j = 0; j < 4; j++) accPV[mt][nt][j] = 0.f;

    const uint32_t pvb_roff = (uint32_t)((((lane >> 4) << 3) + (lane & 7)) * 128
                                         + (((lane >> 3) & 1) << 4));
    #pragma unroll
    for (int g = 0; g < 8; g++) {
        int cglob = wn * 2 + (g >> 2);
        int ksl = g & 3;
        uint32_t bbase = sb + 98304 + cglob * 8192;
        uint32_t aph[2][4];
        #pragma unroll
        for (int mt = 0; mt < 2; mt++) {
            #pragma unroll
            for (int t2 = 0; t2 < 2; t2++) {
                int tile = 2 * g + t2;
                aph[mt][2 * t2]     = packh2(accS[mt][tile][0], accS[mt][tile][1]);
                aph[mt][2 * t2 + 1] = packh2(accS[mt][tile][2], accS[mt][tile][3]);
            }
        }
        #pragma unroll
        for (int bp = 0; bp < 4; bp++) {
            uint32_t b0, b1, b2, b3;
            ldsm_x4(b0, b1, b2, b3, bbase + sw128(pvb_roff + bp * 16 * 128 + ksl * 32));
            #pragma unroll
            for (int mt = 0; mt < 2; mt++) {
                mma16816(accPV[mt][2 * bp],     aph[mt], b0, b1);
                mma16816(accPV[mt][2 * bp + 1], aph[mt], b2, b3);
            }
        }
    }

    __syncthreads();
    float* sred = (float*)ab;
    if (wn == 0) {
        #pragma unroll
        for (int mt = 0; mt < 2; mt++)
            #pragma unroll
            for (int rr = 0; rr < 2; rr++) {
                int rowl = wm * 32 + mt * 16 + rr * 8 + (lane >> 2);
                #pragma unroll
                for (int nt = 0; nt < 8; nt++) {
                    int col = nt * 8 + (lane & 3) * 2;
                    *(float2*)(sred + rowl * 66 + col) =
                        make_float2(accPV[mt][nt][2 * rr], accPV[mt][nt][2 * rr + 1]);
                }
            }
    }
    __syncthreads();
    if (wn == 1) {
        #pragma unroll
        for (int mt = 0; mt < 2; mt++)
            #pragma unroll
            for (int rr = 0; rr < 2; rr++) {
                int rowl = wm * 32 + mt * 16 + rr * 8 + (lane >> 2);
                size_t cbase = (size_t)bt * NN * CB + (size_t)(bm + rowl) * CB
                             + (size_t)head * HDD;
                #pragma unroll
                for (int nt = 0; nt < 8; nt++) {
                    int col = nt * 8 + (lane & 3) * 2;
                    float2 o = *(float2*)(sred + rowl * 66 + col);
                    float v0 = accPV[mt][nt][2 * rr]     + o.x;
                    float v1 = accPV[mt][nt][2 * rr + 1] + o.y;
                    *(__half2*)(cxh + cbase + col) = __floats2half2_rn(v0, v1);
                }
            }
    }
}

// ---------------- prep1: expert sums + dyn softmax + zero out2 ----------------
__global__ void prep1_kernel(const float* __restrict__ qe, const float* __restrict__ ke,
                             const float* __restrict__ y, const float* __restrict__ dw,
                             const float* __restrict__ db, float4* __restrict__ out2z) {
    if (blockIdx.x < 64) {
        int b = blockIdx.x;
        const float* src = (b >> 5) ? ke : qe;
        float* dst = (b >> 5) ? g_ksum : g_qsum;
        int k = (b >> 2) & 7;
        int c = (b & 3) * 256 + threadIdx.x;
        const float* p = src + (size_t)k * CB * CB + c;
        float s = 0.f;
        #pragma unroll 4
        for (int r = 0; r < CB; r++) s += p[(size_t)r * CB];
        dst[k * CB + c] = s;
    } else if (blockIdx.x < 320) {
        int row  = (blockIdx.x - 64) * 8 + (threadIdx.x >> 5);
        int lane = threadIdx.x & 31;
        const float* yr = y + (size_t)row * CB;
        float acc[KEXP];
        #pragma unroll
        for (int j = 0; j < KEXP; j++) acc[j] = 0.f;
        for (int c = lane * 4; c < CB; c += 128) {
            float4 yv = *(const float4*)(yr + c);
            #pragma unroll
            for (int j = 0; j < KEXP; j++) {
                float4 w = *(const float4*)(dw + j * CB + c);
                acc[j] += yv.x * w.x + yv.y * w.y + yv.z * w.z + yv.w * w.w;
            }
        }
        #pragma unroll
        for (int j = 0; j < KEXP; j++)
            #pragma unroll
            for (int off = 16; off > 0; off >>= 1)
                acc[j] += __shfl_xor_sync(0xffffffffu, acc[j], off);
        if (lane == 0) {
            float l[KEXP], m = -1e30f;
            #pragma unroll
            for (int j = 0; j < KEXP; j++) { l[j] = acc[j] + db[j]; m = fmaxf(m, l[j]); }
            float s = 0.f;
            #pragma unroll
            for (int j = 0; j < KEXP; j++) { l[j] = expf(l[j] - m); s += l[j]; }
            float inv = 1.f / s;
            #pragma unroll
            for (int j = 0; j < KEXP; j++) g_dyn[row * KEXP + j] = l[j] * inv;
        }
    } else {
        size_t i = (size_t)(blockIdx.x - 320) * 256 + threadIdx.x;
        out2z[i] = make_float4(0.f, 0.f, 0.f, 0.f);
    }
}

// ---------------- qk_split: scale computed inline ----------------
__global__ void qk_split_kernel(const float* __restrict__ x) {
    size_t idx = (size_t)blockIdx.x * 256 + threadIdx.x;
    size_t row = idx >> 8;
    int c4 = (int)(idx & 255) * 4;
    int srow = (int)(((row >> 12) << 8) | (row & 255));
    const float* d = g_dyn + (size_t)srow * KEXP;
    float4 xv = *(const float4*)(x + row * CB + c4);

    float qs[4] = {0, 0, 0, 0}, ks[4] = {0, 0, 0, 0};
    #pragma unroll
    for (int j = 0; j < KEXP; j++) {
        float dj = d[j];
        float4 qv = *(const float4*)(g_qsum + j * CB + c4);
        float4 kv = *(const float4*)(g_ksum + j * CB + c4);
        qs[0] += dj * qv.x; qs[1] += dj * qv.y; qs[2] += dj * qv.z; qs[3] += dj * qv.w;
        ks[0] += dj * kv.x; ks[1] += dj * kv.y; ks[2] += dj * kv.z; ks[3] += dj * kv.w;
    }

    size_t base = row * CB + c4;
    float xi[4] = {xv.x, xv.y, xv.z, xv.w};
    __half xh[4], qh[4], ql[4], kh[4], kl[4];
    #pragma unroll
    for (int j = 0; j < 4; j++) {
        xh[j] = __float2half_rn(xi[j]);
        float qi = xi[j] * qs[j], ki = xi[j] * ks[j];
        float h;
        h = hfr(qi); qh[j] = __float2half_rn(h); ql[j] = __float2half_rn(qi - h);
        h = hfr(ki); kh[j] = __float2half_rn(h); kl[j] = __float2half_rn(ki - h);
    }
    *(uint2*)(g_xh + base) = *(uint2*)xh;
    *(uint2*)(g_qkh + base)      = *(uint2*)qh;  *(uint2*)(g_qkl + base)      = *(uint2*)ql;
    *(uint2*)(g_qkh + QK + base) = *(uint2*)kh;  *(uint2*)(g_qkl + QK + base) = *(uint2*)kl;
}

// ---------------- wq+wk split ----------------
__global__ void wsplit_kernel(const float* __restrict__ w, __half* __restrict__ h,
                              __half* __restrict__ l, int n) {
    int i = blockIdx.x * 256 + threadIdx.x;
    if (i >= n) return;
    float a  = w[i];
    float hh = hfr(a);
    h[i] = __float2half_rn(hh);
    l[i] = __float2half_rn(a - hh);
}

// ---------------- fused weight prep: wv split | ow round | vw transpose-split | bc ----------------
__global__ void wprep_kernel(const float* __restrict__ wv, const float* __restrict__ ow,
                             const float* __restrict__ vw, const float* __restrict__ vb,
                             const float* __restrict__ bv) {
    __shared__ float tile[32][33];
    int b = blockIdx.x;
    if (b < 4096) {
        int i = b * 256 + threadIdx.x;
        float a = wv[i];
        float hh = hfr(a);
        w_wvh[i] = __float2half_rn(hh);
        w_wvl[i] = __float2half_rn(a - hh);
    } else if (b < 8192) {
        int i = (b - 4096) * 256 + threadIdx.x;
        w_owh[i] = __float2half_rn(ow[i]);
    } else if (b < 9216) {
        int bb = b - 8192;
        int bx = (bb & 31) * 32, by = (bb >> 5) * 32;
        int tx = threadIdx.x & 31, ty = threadIdx.x >> 5;
        #pragma unroll
        for (int i = 0; i < 4; i++)
            tile[ty + i * 8][tx] = vw[(size_t)(by + ty + i * 8) * CB + bx + tx];
        __syncthreads();
        #pragma unroll
        for (int i = 0; i < 4; i++) {
            int orow = bx + ty + i * 8;
            float a = tile[tx][ty + i * 8];
            float h = hfr(a);
            w_vwth[(size_t)orow * CB + by + tx] = __float2half_rn(h);
            w_vwtl[(size_t)orow * CB + by + tx] = __float2half_rn(a - h);
        }
    } else {
        int d = (b - 9216) * 8 + (threadIdx.x >> 5);
        int lane = threadIdx.x & 31;
        const float* wr = wv + (size_t)d * CB;
        float s = 0.f;
        for (int k = lane * 4; k < CB; k += 128) {
            float4 w = *(const float4*)(wr + k);
            float4 v = *(const float4*)(vb + k);
            s += w.x * v.x + w.y * v.y + w.z * v.z + w.w * v.w;
        }
        #pragma unroll
        for (int off = 16; off > 0; off >>= 1) s += __shfl_xor_sync(0xffffffffu, s, off);
        if (lane == 0) g_bc[d] = s + bv[d];
    }
}

// ---------------- LayerNorm ----------------
__device__ __forceinline__ float block_sum(float v) {
    __shared__ float sh[8];
    int lane = threadIdx.x & 31, w = threadIdx.x >> 5;
    #pragma unroll
    for (int off = 16; off > 0; off >>= 1) v += __shfl_xor_sync(0xffffffffu, v, off);
    if (lane == 0) sh[w] = v;
    __syncthreads();
    float t = (threadIdx.x < 8) ? sh[threadIdx.x] : 0.f;
    if (w == 0) {
        #pragma unroll
        for (int off = 4; off > 0; off >>= 1) t += __shfl_xor_sync(0xffffffffu, t, off);
        if (lane == 0) sh[0] = t;
    }
    __syncthreads();
    float r = sh[0];
    __syncthreads();
    return r;
}

__global__ void ln_kernel(float* __restrict__ h, const float* __restrict__ gamma,
                          const float* __restrict__ beta) {
    int row = blockIdx.x;
    float* p = h + (size_t)row * CB;
    float4 v = ((float4*)p)[threadIdx.x];
    float mu = block_sum(v.x + v.y + v.z + v.w) * (1.f / CB);
    float d0 = v.x - mu, d1 = v.y - mu, d2 = v.z - mu, d3 = v.w - mu;
    float var = block_sum(d0 * d0 + d1 * d1 + d2 * d2 + d3 * d3) * (1.f / CB);
    float inv = rsqrtf(var + EPS);
    float4 g  = ((const float4*)gamma)[threadIdx.x];
    float4 be = ((const float4*)beta)[threadIdx.x];
    float4 o;
    o.x = d0 * inv * g.x + be.x;
    o.y = d1 * inv * g.y + be.y;
    o.z = d2 * inv * g.z + be.z;
    o.w = d3 * inv * g.w + be.w;
    ((float4*)p)[threadIdx.x] = o;
}

// ---------------- launch ----------------
extern "C" void kernel_launch(void* const* d_in, const int* in_sizes, int n_in,
                              void* d_out, int out_size) {
    const float* x    = (const float*)d_in[0];
    const float* y    = (const float*)d_in[1];
    const float* q_ex = (const float*)d_in[3];
    const float* k_ex = (const float*)d_in[4];
    const float* dynw = (const float*)d_in[5];
    const float* dynb = (const float*)d_in[6];
    const float* v_w  = (const float*)d_in[7];
    const float* v_b  = (const float*)d_in[8];
    const float* in_w = (const float*)d_in[9];
    const float* in_b = (const float*)d_in[10];
    const float* o_w  = (const float*)d_in[11];
    const float* o_b  = (const float*)d_in[12];
    const float* gam  = (const float*)d_in[13];
    const float* bet  = (const float*)d_in[14];

    float* out1 = (float*)d_out;
    float* out2 = out1 + (size_t)MROWS * CB;

    #define SYM(T, v, s) T* v; cudaGetSymbolAddress((void**)&v, s);
    SYM(float, p_bc, g_bc)
    SYM(__half, p_xh, g_xh)
    SYM(__half, p_qkh, g_qkh)   SYM(__half, p_qkl, g_qkl)
    SYM(__half, p_qpkh, g_qpkh) SYM(__half, p_qpkl, g_qpkl)
    SYM(__half, p_vpth, g_vpth)
    SYM(__half, p_cxh, g_cxh)
    SYM(__half, pw_qkh, w_qkh)  SYM(__half, pw_qkl, w_qkl)
    SYM(__half, pw_wvh, w_wvh)  SYM(__half, pw_wvl, w_wvl)
    SYM(__half, pw_vwth, w_vwth) SYM(__half, pw_vwtl, w_vwtl)
    SYM(__half, pw_wch, w_wch)
    SYM(__half, pw_owh, w_owh)
    #undef SYM

    // NP3 BN=256, 2 stages: stage = 2*16K + 2*32K = 96KB
    const int SM_NP3 = 256 + 2 * (2 * 16384 + 2 * 32768);  // 196864
    const int SM_NP1 = 256 + 3 * (2 * 16384);              //  98560
    const int SM_FL  = 256 + 131072;                       // 131328
    cudaFuncSetAttribute(hmma_f16<3,0,256,2>, cudaFuncAttributeMaxDynamicSharedMemorySize, SM_NP3);
    cudaFuncSetAttribute(hmma_f16<1,0,128,3>, cudaFuncAttributeMaxDynamicSharedMemorySize, SM_NP1);
    cudaFuncSetAttribute(hmma_f16<1,2,128,3>, cudaFuncAttributeMaxDynamicSharedMemorySize, SM_NP1);
    cudaFuncSetAttribute(flash_kernel,        cudaFuncAttributeMaxDynamicSharedMemorySize, SM_FL);

    const int WNi = CB * CB;

    // ---- deps (GEMM at capture slot #4) ----
    prep1_kernel<<<320 + 8192, 256>>>(q_ex, k_ex, y, dynw, dynb, (float4*)out2);
    qk_split_kernel<<<(int)(QK / 4 / 256), 256>>>(x);
    wsplit_kernel<<<2 * WNi / 256, 256>>>(in_w, pw_qkh, pw_qkl, 2 * WNi);

    // ---- 4: qp & kp dual-batch NP3 GEMM (BN=256, 512 threads) ----
    hmma_f16<3,0,256,2><<<dim3(4, 256, 2), 512, SM_NP3>>>(
        p_qkh, p_qkl, pw_qkh, pw_qkl, nullptr, p_qpkh, p_qpkl,
        CB, CB, CB, CB, in_b, nullptr, QK, WNS);

    // ---- fused weight prep ----
    wprep_kernel<<<9344, 256>>>(in_w + 2 * WNS, o_w, v_w, v_b, in_b + 2 * CB);

    // ---- Wc = wv @ vw (NP3 BN=256, rounded single output) ----
    hmma_f16<3,0,256,2><<<dim3(4, 8), 512, SM_NP3>>>(
        pw_wvh, pw_wvl, pw_vwth, pw_vwtl, nullptr, pw_wch, nullptr,
        CB, CB, CB, CB, nullptr, nullptr, 0, 0);

    // ---- vpT = Wc @ x^T + bc (NP1, OMODE2) ----
    hmma_f16<1,2,128,3><<<dim3(256, 8), 256, SM_NP1>>>(
        pw_wch, nullptr, p_xh, nullptr, nullptr, p_vpth, nullptr,
        CB, CB, CB, CB, p_bc, nullptr, 0, 0);

    // ---- flash (staged loads, fused attn_avg) ----
    flash_kernel<<<dim3(2, BTT * HH), 256, SM_FL>>>(
        p_qpkh, p_qpkl, p_qpkh + QK, p_qpkl + QK, p_vpth, out2, p_cxh);

    // ---- h = x + ctx @ out_w^T + out_b (NP1) ----
    hmma_f16<1,0,128,3><<<dim3(8, 256), 256, SM_NP1>>>(
        p_cxh, nullptr, pw_owh, nullptr, out1, nullptr, nullptr,
        CB, CB, CB, CB, o_b, x, 0, 0);
    // ---- LayerNorm in-place ----
    ln_kernel<<<MROWS, 256>>>(out1, gam, bet);
}

// round 15
// speedup vs baseline: 1.1883x; 1.1883x over previous
#include <cuda_runtime.h>
#include <cuda_fp16.h>
#include <math.h>
#include <stddef.h>
#include <stdint.h>

// ---------------- problem constants ----------------
constexpr int BB   = 8;
constexpr int TT   = 16;
constexpr int NN   = 256;
constexpr int CB   = 1024;
constexpr int HH   = 16;
constexpr int HDD  = 64;
constexpr int KEXP = 8;
constexpr int BTT  = BB * TT;          // 128
constexpr int MROWS = BTT * NN;        // 32768
constexpr float EPS = 1e-5f;
constexpr size_t QK  = (size_t)MROWS * CB;
constexpr size_t WNS = (size_t)CB * CB;

// ---------------- device scratch ----------------
__device__ __align__(128) float g_qsum[KEXP * CB];
__device__ __align__(128) float g_ksum[KEXP * CB];
__device__ __align__(128) float g_dyn[BB * NN * KEXP];
__device__ __align__(128) float g_qscale[BB * NN * CB];
__device__ __align__(128) float g_kscale[BB * NN * CB];
__device__ __align__(128) float g_bc[CB];

__device__ __align__(128) __half g_xh  [QK];
__device__ __align__(128) __half g_qkh [2 * QK];      // q then k (scaled splits)
__device__ __align__(128) __half g_qkl [2 * QK];
__device__ __align__(128) __half g_qpkh[2 * QK];      // qp then kp
__device__ __align__(128) __half g_qpkl[2 * QK];
__device__ __align__(128) __half g_vpth[QK];          // vp transposed per bt: [bt][d][key]
__device__ __align__(128) __half g_cxh [QK];          // ctx single fp16
__device__ __align__(128) __half g_ah  [(size_t)BTT * HH * NN * NN];   // probs fp16

__device__ __align__(128) __half w_qkh [2 * WNS];     // wq,wk splits
__device__ __align__(128) __half w_qkl [2 * WNS];
__device__ __align__(128) __half w_wvh [WNS];
__device__ __align__(128) __half w_wvl [WNS];
__device__ __align__(128) __half w_vwth[WNS];
__device__ __align__(128) __half w_vwtl[WNS];
__device__ __align__(128) __half w_wch [WNS];         // Wc rounded single
__device__ __align__(128) __half w_owh [WNS];

// ---------------- helpers ----------------
__device__ __forceinline__ uint32_t smem_u32(const void* p) {
    return (uint32_t)__cvta_generic_to_shared(p);
}
__device__ __forceinline__ uint32_t sw128(uint32_t o) { return o ^ ((o >> 3) & 0x70); }
__device__ __forceinline__ float hfr(float a) { return __half2float(__float2half_rn(a)); }
__device__ __forceinline__ uint32_t packh2(float a, float b) {
    __half2 t = __floats2half2_rn(a, b);
    return *(uint32_t*)&t;
}
__device__ __forceinline__ void ldsm_x4(uint32_t& r0, uint32_t& r1, uint32_t& r2, uint32_t& r3,
                                        uint32_t addr) {
    asm volatile("ldmatrix.sync.aligned.m8n8.x4.shared.b16 {%0,%1,%2,%3}, [%4];"
                 : "=r"(r0), "=r"(r1), "=r"(r2), "=r"(r3) : "r"(addr));
}
__device__ __forceinline__ void mma16816(float* d, const uint32_t* a, uint32_t b0, uint32_t b1) {
    asm volatile("mma.sync.aligned.m16n8k16.row.col.f32.f16.f16.f32 "
                 "{%0,%1,%2,%3}, {%4,%5,%6,%7}, {%8,%9}, {%0,%1,%2,%3};"
                 : "+f"(d[0]), "+f"(d[1]), "+f"(d[2]), "+f"(d[3])
                 : "r"(a[0]), "r"(a[1]), "r"(a[2]), "r"(a[3]), "r"(b0), "r"(b1));
}
__device__ __forceinline__ void cp16(uint32_t dst, const void* src) {
    asm volatile("cp.async.cg.shared.global [%0], [%1], 16;" :: "r"(dst), "l"(src) : "memory");
}
__device__ __forceinline__ void cp_commit() { asm volatile("cp.async.commit_group;" ::: "memory"); }
template<int N> __device__ __forceinline__ void cp_wait() {
    asm volatile("cp.async.wait_group %0;" :: "n"(N) : "memory");
}

// ---------------- fp16 split HMMA GEMM (plain NT), 3-stage cp.async pipeline ----------------
// NPROD=3: (A0+A1)@(B0+B1) via hh,hl,lh.  NPROD=2: (A0+A1)@B0.  NPROD=1: A0@B0.
// OMODE 0: row-major out (Cf fp32 / Ch+Cl split2 / Ch single), bias per COL, optional resid.
//          gridDim.z batching with strides az (A,C), bz (B), bias += z*CB.
// OMODE 2: vpT write — out[col>>8][row][col&255] half (Ch only), bias per ROW.
template<int NPROD, int OMODE>
__global__ void __launch_bounds__(256, NPROD == 1 ? 2 : 1)
hmma_f16(const __half* __restrict__ A0, const __half* __restrict__ A1,
         const __half* __restrict__ B0, const __half* __restrict__ B1,
         float* __restrict__ Cf, __half* __restrict__ Ch, __half* __restrict__ Cl,
         int Kdim, int lda, int ldb, int ldc,
         const float* __restrict__ bias, const float* __restrict__ resid,
         size_t az, size_t bz)
{
    constexpr int NSA = (NPROD >= 2) ? 2 : 1;
    constexpr int NSB = (NPROD == 3) ? 2 : 1;
    constexpr int ATILE = 128 * 64 * 2;
    constexpr int BTILE = 128 * 64 * 2;
    constexpr int STAGE = NSA * ATILE + NSB * BTILE;

    extern __shared__ char dsm[];
    const uint32_t sraw  = smem_u32(dsm);
    const uint32_t sbase = (sraw + 127u) & ~127u;

    const int tid  = threadIdx.x;
    const int wid  = tid >> 5;
    const int lane = tid & 31;
    const int wm   = wid & 3;
    const int wn   = wid >> 2;

    if (OMODE == 0 && blockIdx.z) {
        size_t zo = blockIdx.z * az, zb = blockIdx.z * bz;
        A0 += zo; if (A1) A1 += zo;
        B0 += zb; if (B1) B1 += zb;
        if (Cf) Cf += zo;
        if (Ch) { Ch += zo; if (Cl) Cl += zo; }
        if (bias) bias += blockIdx.z * CB;
    }

    const __half* Ap[2] = {A0, A1};
    const __half* Bp[2] = {B0, B1};
    const int bm = blockIdx.y * 128, bn = blockIdx.x * 128;

    auto issue = [&](int s, int kt) {
        uint32_t st = sbase + s * STAGE;
        #pragma unroll
        for (int p = 0; p < NSA; p++) {
            const __half* As = Ap[p];
            #pragma unroll
            for (int r = 0; r < 4; r++) {
                int i = tid + r * 256;
                int row = i >> 3, ch = (i & 7) * 16;
                cp16(st + p * ATILE + sw128((uint32_t)(row * 128 + ch)),
                     (const char*)(As + (size_t)(bm + row) * lda + kt) + ch);
            }
        }
        #pragma unroll
        for (int p = 0; p < NSB; p++) {
            const __half* Bs = Bp[p];
            #pragma unroll
            for (int r = 0; r < 4; r++) {
                int i = tid + r * 256;
                int row = i >> 3, ch = (i & 7) * 16;
                cp16(st + NSA * ATILE + p * BTILE + sw128((uint32_t)(row * 128 + ch)),
                     (const char*)(Bs + (size_t)(bn + row) * ldb + kt) + ch);
            }
        }
        cp_commit();
    };

    float acc[2][8][4];
    #pragma unroll
    for (int mt = 0; mt < 2; mt++)
        #pragma unroll
        for (int nt = 0; nt < 8; nt++)
            #pragma unroll
            for (int j = 0; j < 4; j++) acc[mt][nt][j] = 0.f;

    const uint32_t a_roff = (uint32_t)((wm * 32 + (lane & 15)) * 128 + ((lane >> 4) << 4));
    const uint32_t b_roff = (uint32_t)((wn * 64 + ((lane >> 4) << 3) + (lane & 7)) * 128
                                       + (((lane >> 3) & 1) << 4));

    auto compute = [&](int s) {
        uint32_t st = sbase + s * STAGE;
        #pragma unroll
        for (int p = 0; p < NPROD; p++) {
            int pa, pb;
            if (NPROD == 3)      { pa = (p == 2) ? 1 : 0; pb = (p == 1) ? 1 : 0; }
            else if (NPROD == 2) { pa = p; pb = 0; }
            else                 { pa = 0; pb = 0; }
            uint32_t abp = st + pa * ATILE;
            uint32_t bbp = st + NSA * ATILE + pb * BTILE;
            #pragma unroll
            for (int ks = 0; ks < 4; ks++) {
                uint32_t a[2][4];
                #pragma unroll
                for (int mt = 0; mt < 2; mt++)
                    ldsm_x4(a[mt][0], a[mt][1], a[mt][2], a[mt][3],
                            abp + sw128(a_roff + mt * 16 * 128 + ks * 32));
                #pragma unroll
                for (int bp = 0; bp < 4; bp++) {
                    uint32_t b0, b1, b2, b3;
                    ldsm_x4(b0, b1, b2, b3, bbp + sw128(b_roff + bp * 16 * 128 + ks * 32));
                    #pragma unroll
                    for (int mt = 0; mt < 2; mt++) {
                        mma16816(acc[mt][2 * bp],     a[mt], b0, b1);
                        mma16816(acc[mt][2 * bp + 1], a[mt], b2, b3);
                    }
                }
            }
        }
    };

    const int nch = Kdim / 64;
    issue(0, 0);
    if (nch > 1) issue(1, 64);
    if (nch > 2) issue(2, 128);
    for (int t = 0; t < nch; t++) {
        int rem = nch - 1 - t;
        if (rem >= 2) cp_wait<2>();
        else if (rem == 1) cp_wait<1>();
        else cp_wait<0>();
        __syncthreads();
        compute(t % 3);
        __syncthreads();
        if (t + 3 < nch) issue(t % 3, (t + 3) * 64);
    }

    // ---- epilogue ----
    #pragma unroll
    for (int mt = 0; mt < 2; mt++) {
        int r0 = bm + wm * 32 + mt * 16 + (lane >> 2);
        #pragma unroll
        for (int nt = 0; nt < 8; nt++) {
            int col = bn + wn * 64 + nt * 8 + (lane & 3) * 2;
            #pragma unroll
            for (int rr = 0; rr < 2; rr++) {
                int row = r0 + rr * 8;
                float v0 = acc[mt][nt][2 * rr];
                float v1 = acc[mt][nt][2 * rr + 1];
                if (OMODE == 2) {
                    float b = bias[row];
                    v0 += b; v1 += b;
                    size_t t0 = (size_t)(col >> 8) * (CB * NN) + (size_t)row * NN + (col & 255);
                    *(__half2*)(Ch + t0) = __floats2half2_rn(v0, v1);
                } else {
                    if (bias)  { v0 += bias[col]; v1 += bias[col + 1]; }
                    if (resid) {
                        const float* rp = resid + (size_t)row * ldc + col;
                        v0 += rp[0]; v1 += rp[1];
                    }
                    size_t base = (size_t)row * ldc + col;
                    if (Cf) *(float2*)(Cf + base) = make_float2(v0, v1);
                    if (Ch && Cl) {
                        float h0 = hfr(v0), h1 = hfr(v1);
                        *(__half2*)(Ch + base) = __floats2half2_rn(h0, h1);
                        *(__half2*)(Cl + base) = __floats2half2_rn(v0 - h0, v1 - h1);
                    } else if (Ch) {
                        *(__half2*)(Ch + base) = __floats2half2_rn(v0, v1);
                    }
                }
            }
        }
    }
}

// ---------------- flash attention (R8 structure, NP1 PV, ctx single fp16) ----------------
// grid (2 m-blocks, BT*H). 128 q-rows x 256 keys x 64 hd.
__global__ void __launch_bounds__(256)
flash_kernel(const __half* __restrict__ qph, const __half* __restrict__ qpl,
             const __half* __restrict__ kph, const __half* __restrict__ kpl,
             const __half* __restrict__ vpt,
             __half* __restrict__ AH, __half* __restrict__ cxh)
{
    // smem: [0,32K) qp splits | [32K,96K) kp splits | [96K,128K) V 4 chunks
    // reuse [0,..) after scores: red[2x128] f32, then sred 128x66 f32
    extern __shared__ char dsm[];
    const uint32_t sraw = smem_u32(dsm);
    const uint32_t sb   = (sraw + 127u) & ~127u;
    char* const ab      = dsm + (sb - sraw);

    const int tid = threadIdx.x, wid = tid >> 5, lane = tid & 31;
    const int wm = wid & 3, wn = wid >> 2;
    const int z = blockIdx.y;
    const int bt = z >> 4, head = z & 15;
    const int bm = blockIdx.x * 128;

    const size_t qoff = (size_t)bt * NN * CB + (size_t)head * HDD;
    const size_t voff = (size_t)bt * CB * NN + (size_t)head * HDD * NN;

    // ---- load all operands ----
    {
        const __half* qs[2] = {qph, qpl};
        #pragma unroll
        for (int p = 0; p < 2; p++)
            #pragma unroll
            for (int r = 0; r < 4; r++) {
                int i = tid + r * 256;
                int row = i >> 3, ch = (i & 7) * 16;
                cp16(sb + p * 16384 + sw128((uint32_t)(row * 128 + ch)),
                     (const char*)(qs[p] + qoff + (size_t)(bm + row) * CB) + ch);
            }
        const __half* ks[2] = {kph, kpl};
        #pragma unroll
        for (int p = 0; p < 2; p++)
            #pragma unroll
            for (int r = 0; r < 8; r++) {
                int i = tid + r * 256;
                int row = i >> 3, ch = (i & 7) * 16;
                cp16(sb + 32768 + p * 32768 + sw128((uint32_t)(row * 128 + ch)),
                     (const char*)(ks[p] + qoff + (size_t)row * CB) + ch);
            }
        #pragma unroll
        for (int c = 0; c < 4; c++)
            #pragma unroll
            for (int r = 0; r < 2; r++) {
                int i = tid + r * 256;
                int row = i >> 3, ch = (i & 7) * 16;
                cp16(sb + 98304 + c * 8192 + sw128((uint32_t)(row * 128 + ch)),
                     (const char*)(vpt + voff + (size_t)row * NN + c * 64) + ch);
            }
        cp_commit();
        cp_wait<0>();
        __syncthreads();
    }

    // ---- scores: S = qp @ kp^T (NP3 on splits), 128 x 256 ----
    float accS[2][16][4];
    #pragma unroll
    for (int mt = 0; mt < 2; mt++)
        #pragma unroll
        for (int nt = 0; nt < 16; nt++)
            #pragma unroll
            for (int j = 0; j < 4; j++) accS[mt][nt][j] = 0.f;

    const uint32_t a_roff = (uint32_t)((wm * 32 + (lane & 15)) * 128 + ((lane >> 4) << 4));
    const uint32_t b_roff = (uint32_t)((wn * 128 + ((lane >> 4) << 3) + (lane & 7)) * 128
                                       + (((lane >> 3) & 1) << 4));
    #pragma unroll
    for (int p = 0; p < 3; p++) {
        uint32_t abp = sb + ((p == 2) ? 16384 : 0);
        uint32_t bbp = sb + 32768 + ((p == 1) ? 32768 : 0);
        #pragma unroll
        for (int ks = 0; ks < 4; ks++) {
            uint32_t a[2][4];
            #pragma unroll
            for (int mt = 0; mt < 2; mt++)
                ldsm_x4(a[mt][0], a[mt][1], a[mt][2], a[mt][3],
                        abp + sw128(a_roff + mt * 16 * 128 + ks * 32));
            #pragma unroll
            for (int bp = 0; bp < 8; bp++) {
                uint32_t b0, b1, b2, b3;
                ldsm_x4(b0, b1, b2, b3, bbp + sw128(b_roff + bp * 16 * 128 + ks * 32));
                #pragma unroll
                for (int mt = 0; mt < 2; mt++) {
                    mma16816(accS[mt][2 * bp],     a[mt], b0, b1);
                    mma16816(accS[mt][2 * bp + 1], a[mt], b2, b3);
                }
            }
        }
    }
    __syncthreads();   // qp/kp smem free

    // ---- softmax (alpha folded into exp) ----
    float* red = (float*)ab;   // 2 x 128 floats
    float rmax[2][2];
    #pragma unroll
    for (int mt = 0; mt < 2; mt++)
        #pragma unroll
        for (int rr = 0; rr < 2; rr++) {
            float m = -1e30f;
            #pragma unroll
            for (int nt = 0; nt < 16; nt++)
                m = fmaxf(m, fmaxf(accS[mt][nt][2 * rr], accS[mt][nt][2 * rr + 1]));
            m = fmaxf(m, __shfl_xor_sync(0xffffffffu, m, 1));
            m = fmaxf(m, __shfl_xor_sync(0xffffffffu, m, 2));
            int rowl = wm * 32 + mt * 16 + rr * 8 + (lane >> 2);
            if ((lane & 3) == 0) red[wn * 128 + rowl] = m;
        }
    __syncthreads();
    #pragma unroll
    for (int mt = 0; mt < 2; mt++)
        #pragma unroll
        for (int rr = 0; rr < 2; rr++) {
            int rowl = wm * 32 + mt * 16 + rr * 8 + (lane >> 2);
            rmax[mt][rr] = fmaxf(red[rowl], red[128 + rowl]);
        }
    __syncthreads();
    #pragma unroll
    for (int mt = 0; mt < 2; mt++)
        #pragma unroll
        for (int rr = 0; rr < 2; rr++) {
            float m = rmax[mt][rr], s = 0.f;
            #pragma unroll
            for (int nt = 0; nt < 16; nt++) {
                float e0 = __expf((accS[mt][nt][2 * rr]     - m) * 0.125f);
                float e1 = __expf((accS[mt][nt][2 * rr + 1] - m) * 0.125f);
                accS[mt][nt][2 * rr]     = e0;
                accS[mt][nt][2 * rr + 1] = e1;
                s += e0 + e1;
            }
            s += __shfl_xor_sync(0xffffffffu, s, 1);
            s += __shfl_xor_sync(0xffffffffu, s, 2);
            int rowl = wm * 32 + mt * 16 + rr * 8 + (lane >> 2);
            if ((lane & 3) == 0) red[wn * 128 + rowl] = s;
        }
    __syncthreads();
    #pragma unroll
    for (int mt = 0; mt < 2; mt++)
        #pragma unroll
        for (int rr = 0; rr < 2; rr++) {
            int rowl = wm * 32 + mt * 16 + rr * 8 + (lane >> 2);
            float inv = 1.f / (red[rowl] + red[128 + rowl]);
            #pragma unroll
            for (int nt = 0; nt < 16; nt++) {
                accS[mt][nt][2 * rr]     *= inv;
                accS[mt][nt][2 * rr + 1] *= inv;
            }
        }

    // ---- write probs (fp16) for attn_avg ----
    #pragma unroll
    for (int mt = 0; mt < 2; mt++)
        #pragma unroll
        for (int rr = 0; rr < 2; rr++) {
            int rowl = wm * 32 + mt * 16 + rr * 8 + (lane >> 2);
            size_t rbase = (size_t)z * (NN * NN) + (size_t)(bm + rowl) * NN
                         + wn * 128 + (lane & 3) * 2;
            #pragma unroll
            for (int nt = 0; nt < 16; nt++)
                *(__half2*)(AH + rbase + nt * 8) =
                    __floats2half2_rn(accS[mt][nt][2 * rr], accS[mt][nt][2 * rr + 1]);
        }

    // ---- PV: ctx = P_hi @ V (NP1, rounded probs) ----
    float accPV[2][8][4];
    #pragma unroll
    for (int mt = 0; mt < 2; mt++)
        #pragma unroll
        for (int nt = 0; nt < 8; nt++)
            #pragma unroll
            for (int j = 0; j < 4; j++) accPV[mt][nt][j] = 0.f;

    const uint32_t pvb_roff = (uint32_t)((((lane >> 4) << 3) + (lane & 7)) * 128
                                         + (((lane >> 3) & 1) << 4));
    #pragma unroll
    for (int g = 0; g < 8; g++) {
        int cglob = wn * 2 + (g >> 2);
        int ksl = g & 3;
        uint32_t bbase = sb + 98304 + cglob * 8192;
        uint32_t aph[2][4];
        #pragma unroll
        for (int mt = 0; mt < 2; mt++) {
            #pragma unroll
            for (int t2 = 0; t2 < 2; t2++) {
                int tile = 2 * g + t2;
                aph[mt][2 * t2]     = packh2(accS[mt][tile][0], accS[mt][tile][1]);
                aph[mt][2 * t2 + 1] = packh2(accS[mt][tile][2], accS[mt][tile][3]);
            }
        }
        #pragma unroll
        for (int bp = 0; bp < 4; bp++) {
            uint32_t b0, b1, b2, b3;
            ldsm_x4(b0, b1, b2, b3, bbase + sw128(pvb_roff + bp * 16 * 128 + ksl * 32));
            #pragma unroll
            for (int mt = 0; mt < 2; mt++) {
                mma16816(accPV[mt][2 * bp],     aph[mt], b0, b1);
                mma16816(accPV[mt][2 * bp + 1], aph[mt], b2, b3);
            }
        }
    }

    // ---- cross-warp (wn) reduction of PV partials, write ctx single fp16 ----
    __syncthreads();
    float* sred = (float*)ab;   // 128 x 66
    if (wn == 0) {
        #pragma unroll
        for (int mt = 0; mt < 2; mt++)
            #pragma unroll
            for (int rr = 0; rr < 2; rr++) {
                int rowl = wm * 32 + mt * 16 + rr * 8 + (lane >> 2);
                #pragma unroll
                for (int nt = 0; nt < 8; nt++) {
                    int col = nt * 8 + (lane & 3) * 2;
                    *(float2*)(sred + rowl * 66 + col) =
                        make_float2(accPV[mt][nt][2 * rr], accPV[mt][nt][2 * rr + 1]);
                }
            }
    }
    __syncthreads();
    if (wn == 1) {
        #pragma unroll
        for (int mt = 0; mt < 2; mt++)
            #pragma unroll
            for (int rr = 0; rr < 2; rr++) {
                int rowl = wm * 32 + mt * 16 + rr * 8 + (lane >> 2);
                size_t cbase = (size_t)bt * NN * CB + (size_t)(bm + rowl) * CB
                             + (size_t)head * HDD;
                #pragma unroll
                for (int nt = 0; nt < 8; nt++) {
                    int col = nt * 8 + (lane & 3) * 2;
                    float2 o = *(float2*)(sred + rowl * 66 + col);
                    float v0 = accPV[mt][nt][2 * rr]     + o.x;
                    float v1 = accPV[mt][nt][2 * rr + 1] + o.y;
                    *(__half2*)(cxh + cbase + col) = __floats2half2_rn(v0, v1);
                }
            }
    }
}

// ---------------- weight split / round ----------------
__global__ void wsplit_kernel(const float* __restrict__ w, __half* __restrict__ h,
                              __half* __restrict__ l, int n) {
    int i = blockIdx.x * 256 + threadIdx.x;
    if (i >= n) return;
    float a  = w[i];
    float hh = hfr(a);
    h[i] = __float2half_rn(hh);
    l[i] = __float2half_rn(a - hh);
}
__global__ void wround_kernel(const float* __restrict__ w, __half* __restrict__ h, int n) {
    int i = blockIdx.x * 256 + threadIdx.x;
    if (i >= n) return;
    h[i] = __float2half_rn(w[i]);
}

// ---------------- transpose + split (vw -> vwT splits) ----------------
__global__ void tsplit_kernel(const float* __restrict__ w,
                              __half* __restrict__ th, __half* __restrict__ tl) {
    __shared__ float tile[32][33];
    int bx = blockIdx.x * 32, by = blockIdx.y * 32;
    int tx = threadIdx.x & 31, ty = threadIdx.x >> 5;
    #pragma unroll
    for (int i = 0; i < 4; i++)
        tile[ty + i * 8][tx] = w[(size_t)(by + ty + i * 8) * CB + bx + tx];
    __syncthreads();
    #pragma unroll
    for (int i = 0; i < 4; i++) {
        int orow = bx + ty + i * 8;
        float a = tile[tx][ty + i * 8];
        float h = hfr(a);
        th[(size_t)orow * CB + by + tx] = __float2half_rn(h);
        tl[(size_t)orow * CB + by + tx] = __float2half_rn(a - h);
    }
}

// ---------------- bc = wv @ v_b + bv ----------------
__global__ void bc_kernel(const float* __restrict__ wv, const float* __restrict__ vb,
                          const float* __restrict__ bv, float* __restrict__ bc) {
    int d = blockIdx.x * 8 + (threadIdx.x >> 5);
    int lane = threadIdx.x & 31;
    const float* wr = wv + (size_t)d * CB;
    float s = 0.f;
    for (int k = lane * 4; k < CB; k += 128) {
        float4 w = *(const float4*)(wr + k);
        float4 v = *(const float4*)(vb + k);
        s += w.x * v.x + w.y * v.y + w.z * v.z + w.w * v.w;
    }
    #pragma unroll
    for (int off = 16; off > 0; off >>= 1) s += __shfl_xor_sync(0xffffffffu, s, off);
    if (lane == 0) bc[d] = s + bv[d];
}

// ---------------- x round + q/k splits (scale fused, packed arrays) ----------------
__global__ void qk_split_kernel(const float* __restrict__ x) {
    size_t idx = (size_t)blockIdx.x * 256 + threadIdx.x;
    size_t row = idx >> 8;
    int c4 = (int)(idx & 255) * 4;
    int srow = (int)(((row >> 12) << 8) | (row & 255));
    float4 xv = *(const float4*)(x + row * CB + c4);
    float4 qs = *(const float4*)(g_qscale + (size_t)srow * CB + c4);
    float4 ks = *(const float4*)(g_kscale + (size_t)srow * CB + c4);
    size_t base = row * CB + c4;

    float xi[4] = {xv.x, xv.y, xv.z, xv.w};
    float qi[4] = {xv.x * qs.x, xv.y * qs.y, xv.z * qs.z, xv.w * qs.w};
    float ki[4] = {xv.x * ks.x, xv.y * ks.y, xv.z * ks.z, xv.w * ks.w};

    __half xh[4], qh[4], ql[4], kh[4], kl[4];
    #pragma unroll
    for (int j = 0; j < 4; j++) {
        xh[j] = __float2half_rn(xi[j]);
        float h;
        h = hfr(qi[j]); qh[j] = __float2half_rn(h); ql[j] = __float2half_rn(qi[j] - h);
        h = hfr(ki[j]); kh[j] = __float2half_rn(h); kl[j] = __float2half_rn(ki[j] - h);
    }
    *(uint2*)(g_xh + base) = *(uint2*)xh;
    *(uint2*)(g_qkh + base)      = *(uint2*)qh;  *(uint2*)(g_qkl + base)      = *(uint2*)ql;
    *(uint2*)(g_qkh + QK + base) = *(uint2*)kh;  *(uint2*)(g_qkl + QK + base) = *(uint2*)kl;
}

// ---------------- expert sums ----------------
__global__ void expert_sum_kernel(const float* __restrict__ qe, const float* __restrict__ ke) {
    int c = blockIdx.x * 256 + threadIdx.x;
    int k = blockIdx.y;
    const float* src = blockIdx.z ? ke : qe;
    float* dst = blockIdx.z ? g_ksum : g_qsum;
    const float* p = src + (size_t)k * CB * CB + c;
    float s = 0.f;
    #pragma unroll 4
    for (int r = 0; r < CB; r++) s += p[(size_t)r * CB];
    dst[k * CB + c] = s;
}

// ---------------- dyn softmax ----------------
__global__ void dyn_kernel(const float* __restrict__ y, const float* __restrict__ dw,
                           const float* __restrict__ db) {
    int row  = blockIdx.x * 8 + (threadIdx.x >> 5);
    int lane = threadIdx.x & 31;
    const float* yr = y + (size_t)row * CB;
    float acc[KEXP];
    #pragma unroll
    for (int j = 0; j < KEXP; j++) acc[j] = 0.f;
    for (int c = lane * 4; c < CB; c += 128) {
        float4 yv = *(const float4*)(yr + c);
        #pragma unroll
        for (int j = 0; j < KEXP; j++) {
            float4 w = *(const float4*)(dw + j * CB + c);
            acc[j] += yv.x * w.x + yv.y * w.y + yv.z * w.z + yv.w * w.w;
        }
    }
    #pragma unroll
    for (int j = 0; j < KEXP; j++)
        #pragma unroll
        for (int off = 16; off > 0; off >>= 1)
            acc[j] += __shfl_xor_sync(0xffffffffu, acc[j], off);
    if (lane == 0) {
        float l[KEXP], m = -1e30f;
        #pragma unroll
        for (int j = 0; j < KEXP; j++) { l[j] = acc[j] + db[j]; m = fmaxf(m, l[j]); }
        float s = 0.f;
        #pragma unroll
        for (int j = 0; j < KEXP; j++) { l[j] = expf(l[j] - m); s += l[j]; }
        float inv = 1.f / s;
        #pragma unroll
        for (int j = 0; j < KEXP; j++) g_dyn[row * KEXP + j] = l[j] * inv;
    }
}

// ---------------- q/k scales ----------------
__global__ void scale_kernel() {
    int c  = blockIdx.x * 256 + threadIdx.x;
    int bn = blockIdx.y;
    const float* d = g_dyn + bn * KEXP;
    float qs = 0.f, ks = 0.f;
    #pragma unroll
    for (int j = 0; j < KEXP; j++) {
        float dj = d[j];
        qs += dj * g_qsum[j * CB + c];
        ks += dj * g_ksum[j * CB + c];
    }
    g_qscale[(size_t)bn * CB + c] = qs;
    g_kscale[(size_t)bn * CB + c] = ks;
}

// ---------------- attn_avg (half2 vectorized) ----------------
__global__ void attn_avg_kernel(const __half* __restrict__ AH, float* __restrict__ out2) {
    size_t e = ((size_t)blockIdx.x * 256 + threadIdx.x) * 2;
    size_t bt  = e >> 16;
    size_t rem = e & 65535;
    size_t base = bt * ((size_t)HH * NN * NN) + rem;
    float s0 = 0.f, s1 = 0.f;
    #pragma unroll
    for (int h = 0; h < HH; h++) {
        __half2 v = *(const __half2*)(AH + base + (size_t)h * NN * NN);
        float2 f = __half22float2(v);
        s0 += f.x; s1 += f.y;
    }
    *(float2*)(out2 + e) = make_float2(s0 * (1.f / HH), s1 * (1.f / HH));
}

// ---------------- LayerNorm ----------------
__device__ __forceinline__ float block_sum(float v) {
    __shared__ float sh[8];
    int lane = threadIdx.x & 31, w = threadIdx.x >> 5;
    #pragma unroll
    for (int off = 16; off > 0; off >>= 1) v += __shfl_xor_sync(0xffffffffu, v, off);
    if (lane == 0) sh[w] = v;
    __syncthreads();
    float t = (threadIdx.x < 8) ? sh[threadIdx.x] : 0.f;
    if (w == 0) {
        #pragma unroll
        for (int off = 4; off > 0; off >>= 1) t += __shfl_xor_sync(0xffffffffu, t, off);
        if (lane == 0) sh[0] = t;
    }
    __syncthreads();
    float r = sh[0];
    __syncthreads();
    return r;
}

__global__ void ln_kernel(float* __restrict__ h, const float* __restrict__ gamma,
                          const float* __restrict__ beta) {
    int row = blockIdx.x;
    float* p = h + (size_t)row * CB;
    float4 v = ((float4*)p)[threadIdx.x];
    float mu = block_sum(v.x + v.y + v.z + v.w) * (1.f / CB);
    float d0 = v.x - mu, d1 = v.y - mu, d2 = v.z - mu, d3 = v.w - mu;
    float var = block_sum(d0 * d0 + d1 * d1 + d2 * d2 + d3 * d3) * (1.f / CB);
    float inv = rsqrtf(var + EPS);
    float4 g  = ((const float4*)gamma)[threadIdx.x];
    float4 be = ((const float4*)beta)[threadIdx.x];
    float4 o;
    o.x = d0 * inv * g.x + be.x;
    o.y = d1 * inv * g.y + be.y;
    o.z = d2 * inv * g.z + be.z;
    o.w = d3 * inv * g.w + be.w;
    ((float4*)p)[threadIdx.x] = o;
}

// ---------------- launch ----------------
extern "C" void kernel_launch(void* const* d_in, const int* in_sizes, int n_in,
                              void* d_out, int out_size) {
    const float* x    = (const float*)d_in[0];
    const float* y    = (const float*)d_in[1];
    const float* q_ex = (const float*)d_in[3];
    const float* k_ex = (const float*)d_in[4];
    const float* dynw = (const float*)d_in[5];
    const float* dynb = (const float*)d_in[6];
    const float* v_w  = (const float*)d_in[7];
    const float* v_b  = (const float*)d_in[8];
    const float* in_w = (const float*)d_in[9];
    const float* in_b = (const float*)d_in[10];
    const float* o_w  = (const float*)d_in[11];
    const float* o_b  = (const float*)d_in[12];
    const float* gam  = (const float*)d_in[13];
    const float* bet  = (const float*)d_in[14];

    float* out1 = (float*)d_out;
    float* out2 = out1 + (size_t)MROWS * CB;

    #define SYM(T, v, s) T* v; cudaGetSymbolAddress((void**)&v, s);
    SYM(float, p_bc, g_bc)
    SYM(__half, p_xh, g_xh)
    SYM(__half, p_qkh, g_qkh)   SYM(__half, p_qkl, g_qkl)
    SYM(__half, p_qpkh, g_qpkh) SYM(__half, p_qpkl, g_qpkl)
    SYM(__half, p_vpth, g_vpth)
    SYM(__half, p_cxh, g_cxh)
    SYM(__half, p_ah, g_ah)
    SYM(__half, pw_qkh, w_qkh)  SYM(__half, pw_qkl, w_qkl)
    SYM(__half, pw_wvh, w_wvh)  SYM(__half, pw_wvl, w_wvl)
    SYM(__half, pw_vwth, w_vwth) SYM(__half, pw_vwtl, w_vwtl)
    SYM(__half, pw_wch, w_wch)
    SYM(__half, pw_owh, w_owh)
    #undef SYM

    const int SM_NP3 = 256 + 3 * (4 * 16384);   // 196864
    const int SM_NP1 = 256 + 3 * (2 * 16384);   //  98560
    const int SM_FL  = 256 + 131072;            // 131328
    cudaFuncSetAttribute(hmma_f16<3,0>, cudaFuncAttributeMaxDynamicSharedMemorySize, SM_NP3);
    cudaFuncSetAttribute(hmma_f16<1,0>, cudaFuncAttributeMaxDynamicSharedMemorySize, SM_NP1);
    cudaFuncSetAttribute(hmma_f16<1,2>, cudaFuncAttributeMaxDynamicSharedMemorySize, SM_NP1);
    cudaFuncSetAttribute(flash_kernel,  cudaFuncAttributeMaxDynamicSharedMemorySize, SM_FL);

    // ---- prep ----
    expert_sum_kernel<<<dim3(CB / 256, KEXP, 2), 256>>>(q_ex, k_ex);
    dyn_kernel<<<(BB * NN) / 8, 256>>>(y, dynw, dynb);
    scale_kernel<<<dim3(CB / 256, BB * NN), 256>>>();

    const int WNi = CB * CB;
    wsplit_kernel<<<2 * WNi / 256, 256>>>(in_w, pw_qkh, pw_qkl, 2 * WNi);       // wq + wk
    wsplit_kernel<<<WNi / 256, 256>>>(in_w + 2 * WNS, pw_wvh, pw_wvl, WNi);     // wv
    wround_kernel<<<WNi / 256, 256>>>(o_w, pw_owh, WNi);
    tsplit_kernel<<<dim3(32, 32), 256>>>(v_w, pw_vwth, pw_vwtl);
    bc_kernel<<<CB / 8, 256>>>(in_w + 2 * WNS, v_b, in_b + 2 * CB, p_bc);
    qk_split_kernel<<<(int)(QK / 4 / 256), 256>>>(x);

    // ---- Wc = wv @ vw (NP3, rounded single output) ----
    hmma_f16<3,0><<<dim3(8, 8), 256, SM_NP3>>>(
        pw_wvh, pw_wvl, pw_vwth, pw_vwtl, nullptr, pw_wch, nullptr,
        CB, CB, CB, CB, nullptr, nullptr, 0, 0);

    // ---- vpT = Wc @ x^T + bc (NP1, OMODE2) ----
    hmma_f16<1,2><<<dim3(256, 8), 256, SM_NP1>>>(
        pw_wch, nullptr, p_xh, nullptr, nullptr, p_vpth, nullptr,
        CB, CB, CB, CB, p_bc, nullptr, 0, 0);

    // ---- qp & kp in ONE dual-batch NP3 launch ----
    hmma_f16<3,0><<<dim3(8, 256, 2), 256, SM_NP3>>>(
        p_qkh, p_qkl, pw_qkh, pw_qkl, nullptr, p_qpkh, p_qpkl,
        CB, CB, CB, CB, in_b, nullptr, QK, WNS);

    // ---- flash attention ----
    flash_kernel<<<dim3(2, BTT * HH), 256, SM_FL>>>(
        p_qpkh, p_qpkl, p_qpkh + QK, p_qpkl + QK, p_vpth, p_ah, p_cxh);

    // ---- attn_avg ----
    attn_avg_kernel<<<(BTT * NN * NN / 2) / 256, 256>>>(p_ah, out2);

    // ---- h = x + ctx @ out_w^T + out_b (NP1) ----
    hmma_f16<1,0><<<dim3(8, 256), 256, SM_NP1>>>(
        p_cxh, nullptr, pw_owh, nullptr, out1, nullptr, nullptr,
        CB, CB, CB, CB, o_b, x, 0, 0);
    // ---- LayerNorm in-place ----
    ln_kernel<<<MROWS, 256>>>(out1, gam, bet);
}

// round 16
// speedup vs baseline: 1.2275x; 1.0330x over previous
#include <cuda_runtime.h>
#include <cuda_fp16.h>
#include <math.h>
#include <stddef.h>
#include <stdint.h>

// ---------------- problem constants ----------------
constexpr int BB   = 8;
constexpr int TT   = 16;
constexpr int NN   = 256;
constexpr int CB   = 1024;
constexpr int HH   = 16;
constexpr int HDD  = 64;
constexpr int KEXP = 8;
constexpr int BTT  = BB * TT;          // 128
constexpr int MROWS = BTT * NN;        // 32768
constexpr float EPS = 1e-5f;
constexpr size_t QK  = (size_t)MROWS * CB;
constexpr size_t WNS = (size_t)CB * CB;

// ---------------- device scratch ----------------
__device__ __align__(128) float g_qsum[KEXP * CB];
__device__ __align__(128) float g_ksum[KEXP * CB];
__device__ __align__(128) float g_dyn[BB * NN * KEXP];
__device__ __align__(128) float g_qscale[BB * NN * CB];
__device__ __align__(128) float g_kscale[BB * NN * CB];
__device__ __align__(128) float g_bc[CB];

__device__ __align__(128) __half g_xh  [QK];
__device__ __align__(128) __half g_qkh [2 * QK];      // q then k (scaled splits)
__device__ __align__(128) __half g_qkl [2 * QK];
__device__ __align__(128) __half g_qpkh[2 * QK];      // qp then kp
__device__ __align__(128) __half g_qpkl[2 * QK];
__device__ __align__(128) __half g_vpth[QK];          // vp transposed per bt: [bt][d][key]
__device__ __align__(128) __half g_cxh [QK];          // ctx single fp16
__device__ __align__(128) __half g_ah  [(size_t)BTT * HH * NN * NN];   // probs fp16

__device__ __align__(128) __half w_qkh [2 * WNS];     // wq,wk splits
__device__ __align__(128) __half w_qkl [2 * WNS];
__device__ __align__(128) __half w_wvh [WNS];
__device__ __align__(128) __half w_wvl [WNS];
__device__ __align__(128) __half w_vwth[WNS];
__device__ __align__(128) __half w_vwtl[WNS];
__device__ __align__(128) __half w_wch [WNS];         // Wc rounded single
__device__ __align__(128) __half w_owh [WNS];

// ---------------- helpers ----------------
__device__ __forceinline__ uint32_t smem_u32(const void* p) {
    return (uint32_t)__cvta_generic_to_shared(p);
}
__device__ __forceinline__ uint32_t sw128(uint32_t o) { return o ^ ((o >> 3) & 0x70); }
__device__ __forceinline__ float hfr(float a) { return __half2float(__float2half_rn(a)); }
__device__ __forceinline__ uint32_t packh2(float a, float b) {
    __half2 t = __floats2half2_rn(a, b);
    return *(uint32_t*)&t;
}
__device__ __forceinline__ void ldsm_x4(uint32_t& r0, uint32_t& r1, uint32_t& r2, uint32_t& r3,
                                        uint32_t addr) {
    asm volatile("ldmatrix.sync.aligned.m8n8.x4.shared.b16 {%0,%1,%2,%3}, [%4];"
                 : "=r"(r0), "=r"(r1), "=r"(r2), "=r"(r3) : "r"(addr));
}
__device__ __forceinline__ void mma16816(float* d, const uint32_t* a, uint32_t b0, uint32_t b1) {
    asm volatile("mma.sync.aligned.m16n8k16.row.col.f32.f16.f16.f32 "
                 "{%0,%1,%2,%3}, {%4,%5,%6,%7}, {%8,%9}, {%0,%1,%2,%3};"
                 : "+f"(d[0]), "+f"(d[1]), "+f"(d[2]), "+f"(d[3])
                 : "r"(a[0]), "r"(a[1]), "r"(a[2]), "r"(a[3]), "r"(b0), "r"(b1));
}
__device__ __forceinline__ void cp16(uint32_t dst, const void* src) {
    asm volatile("cp.async.cg.shared.global [%0], [%1], 16;" :: "r"(dst), "l"(src) : "memory");
}
__device__ __forceinline__ void cp_commit() { asm volatile("cp.async.commit_group;" ::: "memory"); }
template<int N> __device__ __forceinline__ void cp_wait() {
    asm volatile("cp.async.wait_group %0;" :: "n"(N) : "memory");
}

// ---------------- fp16 split HMMA GEMM (plain NT), 3-stage cp.async pipeline ----------------
// NPROD=3: (A0+A1)@(B0+B1) via hh,hl,lh.  NPROD=2: (A0+A1)@B0.  NPROD=1: A0@B0.
// OMODE 0: row-major out (Cf fp32 / Ch+Cl split2 / Ch single), bias per COL, optional resid.
//          gridDim.z batching with strides az (A,C), bz (B), bias += z*CB.
// OMODE 2: vpT write — out[col>>8][row][col&255] half (Ch only), bias per ROW.
template<int NPROD, int OMODE>
__global__ void __launch_bounds__(256, NPROD == 1 ? 2 : 1)
hmma_f16(const __half* __restrict__ A0, const __half* __restrict__ A1,
         const __half* __restrict__ B0, const __half* __restrict__ B1,
         float* __restrict__ Cf, __half* __restrict__ Ch, __half* __restrict__ Cl,
         int Kdim, int lda, int ldb, int ldc,
         const float* __restrict__ bias, const float* __restrict__ resid,
         size_t az, size_t bz)
{
    constexpr int NSA = (NPROD >= 2) ? 2 : 1;
    constexpr int NSB = (NPROD == 3) ? 2 : 1;
    constexpr int ATILE = 128 * 64 * 2;
    constexpr int BTILE = 128 * 64 * 2;
    constexpr int STAGE = NSA * ATILE + NSB * BTILE;

    extern __shared__ char dsm[];
    const uint32_t sraw  = smem_u32(dsm);
    const uint32_t sbase = (sraw + 127u) & ~127u;

    const int tid  = threadIdx.x;
    const int wid  = tid >> 5;
    const int lane = tid & 31;
    const int wm   = wid & 3;
    const int wn   = wid >> 2;

    if (OMODE == 0 && blockIdx.z) {
        size_t zo = blockIdx.z * az, zb = blockIdx.z * bz;
        A0 += zo; if (A1) A1 += zo;
        B0 += zb; if (B1) B1 += zb;
        if (Cf) Cf += zo;
        if (Ch) { Ch += zo; if (Cl) Cl += zo; }
        if (bias) bias += blockIdx.z * CB;
    }

    const __half* Ap[2] = {A0, A1};
    const __half* Bp[2] = {B0, B1};
    const int bm = blockIdx.y * 128, bn = blockIdx.x * 128;

    auto issue = [&](int s, int kt) {
        uint32_t st = sbase + s * STAGE;
        #pragma unroll
        for (int p = 0; p < NSA; p++) {
            const __half* As = Ap[p];
            #pragma unroll
            for (int r = 0; r < 4; r++) {
                int i = tid + r * 256;
                int row = i >> 3, ch = (i & 7) * 16;
                cp16(st + p * ATILE + sw128((uint32_t)(row * 128 + ch)),
                     (const char*)(As + (size_t)(bm + row) * lda + kt) + ch);
            }
        }
        #pragma unroll
        for (int p = 0; p < NSB; p++) {
            const __half* Bs = Bp[p];
            #pragma unroll
            for (int r = 0; r < 4; r++) {
                int i = tid + r * 256;
                int row = i >> 3, ch = (i & 7) * 16;
                cp16(st + NSA * ATILE + p * BTILE + sw128((uint32_t)(row * 128 + ch)),
                     (const char*)(Bs + (size_t)(bn + row) * ldb + kt) + ch);
            }
        }
        cp_commit();
    };

    float acc[2][8][4];
    #pragma unroll
    for (int mt = 0; mt < 2; mt++)
        #pragma unroll
        for (int nt = 0; nt < 8; nt++)
            #pragma unroll
            for (int j = 0; j < 4; j++) acc[mt][nt][j] = 0.f;

    const uint32_t a_roff = (uint32_t)((wm * 32 + (lane & 15)) * 128 + ((lane >> 4) << 4));
    const uint32_t b_roff = (uint32_t)((wn * 64 + ((lane >> 4) << 3) + (lane & 7)) * 128
                                       + (((lane >> 3) & 1) << 4));

    auto compute = [&](int s) {
        uint32_t st = sbase + s * STAGE;
        #pragma unroll
        for (int p = 0; p < NPROD; p++) {
            int pa, pb;
            if (NPROD == 3)      { pa = (p == 2) ? 1 : 0; pb = (p == 1) ? 1 : 0; }
            else if (NPROD == 2) { pa = p; pb = 0; }
            else                 { pa = 0; pb = 0; }
            uint32_t abp = st + pa * ATILE;
            uint32_t bbp = st + NSA * ATILE + pb * BTILE;
            #pragma unroll
            for (int ks = 0; ks < 4; ks++) {
                uint32_t a[2][4];
                #pragma unroll
                for (int mt = 0; mt < 2; mt++)
                    ldsm_x4(a[mt][0], a[mt][1], a[mt][2], a[mt][3],
                            abp + sw128(a_roff + mt * 16 * 128 + ks * 32));
                #pragma unroll
                for (int bp = 0; bp < 4; bp++) {
                    uint32_t b0, b1, b2, b3;
                    ldsm_x4(b0, b1, b2, b3, bbp + sw128(b_roff + bp * 16 * 128 + ks * 32));
                    #pragma unroll
                    for (int mt = 0; mt < 2; mt++) {
                        mma16816(acc[mt][2 * bp],     a[mt], b0, b1);
                        mma16816(acc[mt][2 * bp + 1], a[mt], b2, b3);
                    }
                }
            }
        }
    };

    const int nch = Kdim / 64;
    issue(0, 0);
    if (nch > 1) issue(1, 64);
    if (nch > 2) issue(2, 128);
    for (int t = 0; t < nch; t++) {
        int rem = nch - 1 - t;
        if (rem >= 2) cp_wait<2>();
        else if (rem == 1) cp_wait<1>();
        else cp_wait<0>();
        __syncthreads();
        compute(t % 3);
        if (t + 3 < nch) {          // sync only needed before re-issuing into this stage
            __syncthreads();
            issue(t % 3, (t + 3) * 64);
        }
    }

    // ---- epilogue ----
    #pragma unroll
    for (int mt = 0; mt < 2; mt++) {
        int r0 = bm + wm * 32 + mt * 16 + (lane >> 2);
        #pragma unroll
        for (int nt = 0; nt < 8; nt++) {
            int col = bn + wn * 64 + nt * 8 + (lane & 3) * 2;
            #pragma unroll
            for (int rr = 0; rr < 2; rr++) {
                int row = r0 + rr * 8;
                float v0 = acc[mt][nt][2 * rr];
                float v1 = acc[mt][nt][2 * rr + 1];
                if (OMODE == 2) {
                    float b = bias[row];
                    v0 += b; v1 += b;
                    size_t t0 = (size_t)(col >> 8) * (CB * NN) + (size_t)row * NN + (col & 255);
                    *(__half2*)(Ch + t0) = __floats2half2_rn(v0, v1);
                } else {
                    if (bias)  { v0 += bias[col]; v1 += bias[col + 1]; }
                    if (resid) {
                        const float* rp = resid + (size_t)row * ldc + col;
                        v0 += rp[0]; v1 += rp[1];
                    }
                    size_t base = (size_t)row * ldc + col;
                    if (Cf) *(float2*)(Cf + base) = make_float2(v0, v1);
                    if (Ch && Cl) {
                        float h0 = hfr(v0), h1 = hfr(v1);
                        *(__half2*)(Ch + base) = __floats2half2_rn(h0, h1);
                        *(__half2*)(Cl + base) = __floats2half2_rn(v0 - h0, v1 - h1);
                    } else if (Ch) {
                        *(__half2*)(Ch + base) = __floats2half2_rn(v0, v1);
                    }
                }
            }
        }
    }
}

// ---------------- flash attention (scores NP3 + softmax + NP1 PV, ctx single fp16) ----------------
__global__ void __launch_bounds__(256)
flash_kernel(const __half* __restrict__ qph, const __half* __restrict__ qpl,
             const __half* __restrict__ kph, const __half* __restrict__ kpl,
             const __half* __restrict__ vpt,
             __half* __restrict__ AH, __half* __restrict__ cxh)
{
    extern __shared__ char dsm[];
    const uint32_t sraw = smem_u32(dsm);
    const uint32_t sb   = (sraw + 127u) & ~127u;
    char* const ab      = dsm + (sb - sraw);

    const int tid = threadIdx.x, wid = tid >> 5, lane = tid & 31;
    const int wm = wid & 3, wn = wid >> 2;
    const int z = blockIdx.y;
    const int bt = z >> 4, head = z & 15;
    const int bm = blockIdx.x * 128;

    const size_t qoff = (size_t)bt * NN * CB + (size_t)head * HDD;
    const size_t voff = (size_t)bt * CB * NN + (size_t)head * HDD * NN;

    {
        const __half* qs[2] = {qph, qpl};
        #pragma unroll
        for (int p = 0; p < 2; p++)
            #pragma unroll
            for (int r = 0; r < 4; r++) {
                int i = tid + r * 256;
                int row = i >> 3, ch = (i & 7) * 16;
                cp16(sb + p * 16384 + sw128((uint32_t)(row * 128 + ch)),
                     (const char*)(qs[p] + qoff + (size_t)(bm + row) * CB) + ch);
            }
        const __half* ks[2] = {kph, kpl};
        #pragma unroll
        for (int p = 0; p < 2; p++)
            #pragma unroll
            for (int r = 0; r < 8; r++) {
                int i = tid + r * 256;
                int row = i >> 3, ch = (i & 7) * 16;
                cp16(sb + 32768 + p * 32768 + sw128((uint32_t)(row * 128 + ch)),
                     (const char*)(ks[p] + qoff + (size_t)row * CB) + ch);
            }
        #pragma unroll
        for (int c = 0; c < 4; c++)
            #pragma unroll
            for (int r = 0; r < 2; r++) {
                int i = tid + r * 256;
                int row = i >> 3, ch = (i & 7) * 16;
                cp16(sb + 98304 + c * 8192 + sw128((uint32_t)(row * 128 + ch)),
                     (const char*)(vpt + voff + (size_t)row * NN + c * 64) + ch);
            }
        cp_commit();
        cp_wait<0>();
        __syncthreads();
    }

    float accS[2][16][4];
    #pragma unroll
    for (int mt = 0; mt < 2; mt++)
        #pragma unroll
        for (int nt = 0; nt < 16; nt++)
            #pragma unroll
            for (int j = 0; j < 4; j++) accS[mt][nt][j] = 0.f;

    const uint32_t a_roff = (uint32_t)((wm * 32 + (lane & 15)) * 128 + ((lane >> 4) << 4));
    const uint32_t b_roff = (uint32_t)((wn * 128 + ((lane >> 4) << 3) + (lane & 7)) * 128
                                       + (((lane >> 3) & 1) << 4));
    #pragma unroll
    for (int p = 0; p < 3; p++) {
        uint32_t abp = sb + ((p == 2) ? 16384 : 0);
        uint32_t bbp = sb + 32768 + ((p == 1) ? 32768 : 0);
        #pragma unroll
        for (int ks = 0; ks < 4; ks++) {
            uint32_t a[2][4];
            #pragma unroll
            for (int mt = 0; mt < 2; mt++)
                ldsm_x4(a[mt][0], a[mt][1], a[mt][2], a[mt][3],
                        abp + sw128(a_roff + mt * 16 * 128 + ks * 32));
            #pragma unroll
            for (int bp = 0; bp < 8; bp++) {
                uint32_t b0, b1, b2, b3;
                ldsm_x4(b0, b1, b2, b3, bbp + sw128(b_roff + bp * 16 * 128 + ks * 32));
                #pragma unroll
                for (int mt = 0; mt < 2; mt++) {
                    mma16816(accS[mt][2 * bp],     a[mt], b0, b1);
                    mma16816(accS[mt][2 * bp + 1], a[mt], b2, b3);
                }
            }
        }
    }
    __syncthreads();

    float* red = (float*)ab;
    float rmax[2][2];
    #pragma unroll
    for (int mt = 0; mt < 2; mt++)
        #pragma unroll
        for (int rr = 0; rr < 2; rr++) {
            float m = -1e30f;
            #pragma unroll
            for (int nt = 0; nt < 16; nt++)
                m = fmaxf(m, fmaxf(accS[mt][nt][2 * rr], accS[mt][nt][2 * rr + 1]));
            m = fmaxf(m, __shfl_xor_sync(0xffffffffu, m, 1));
            m = fmaxf(m, __shfl_xor_sync(0xffffffffu, m, 2));
            int rowl = wm * 32 + mt * 16 + rr * 8 + (lane >> 2);
            if ((lane & 3) == 0) red[wn * 128 + rowl] = m;
        }
    __syncthreads();
    #pragma unroll
    for (int mt = 0; mt < 2; mt++)
        #pragma unroll
        for (int rr = 0; rr < 2; rr++) {
            int rowl = wm * 32 + mt * 16 + rr * 8 + (lane >> 2);
            rmax[mt][rr] = fmaxf(red[rowl], red[128 + rowl]);
        }
    __syncthreads();
    #pragma unroll
    for (int mt = 0; mt < 2; mt++)
        #pragma unroll
        for (int rr = 0; rr < 2; rr++) {
            float m = rmax[mt][rr], s = 0.f;
            #pragma unroll
            for (int nt = 0; nt < 16; nt++) {
                float e0 = __expf((accS[mt][nt][2 * rr]     - m) * 0.125f);
                float e1 = __expf((accS[mt][nt][2 * rr + 1] - m) * 0.125f);
                accS[mt][nt][2 * rr]     = e0;
                accS[mt][nt][2 * rr + 1] = e1;
                s += e0 + e1;
            }
            s += __shfl_xor_sync(0xffffffffu, s, 1);
            s += __shfl_xor_sync(0xffffffffu, s, 2);
            int rowl = wm * 32 + mt * 16 + rr * 8 + (lane >> 2);
            if ((lane & 3) == 0) red[wn * 128 + rowl] = s;
        }
    __syncthreads();
    #pragma unroll
    for (int mt = 0; mt < 2; mt++)
        #pragma unroll
        for (int rr = 0; rr < 2; rr++) {
            int rowl = wm * 32 + mt * 16 + rr * 8 + (lane >> 2);
            float inv = 1.f / (red[rowl] + red[128 + rowl]);
            #pragma unroll
            for (int nt = 0; nt < 16; nt++) {
                accS[mt][nt][2 * rr]     *= inv;
                accS[mt][nt][2 * rr + 1] *= inv;
            }
        }

    #pragma unroll
    for (int mt = 0; mt < 2; mt++)
        #pragma unroll
        for (int rr = 0; rr < 2; rr++) {
            int rowl = wm * 32 + mt * 16 + rr * 8 + (lane >> 2);
            size_t rbase = (size_t)z * (NN * NN) + (size_t)(bm + rowl) * NN
                         + wn * 128 + (lane & 3) * 2;
            #pragma unroll
            for (int nt = 0; nt < 16; nt++)
                *(__half2*)(AH + rbase + nt * 8) =
                    __floats2half2_rn(accS[mt][nt][2 * rr], accS[mt][nt][2 * rr + 1]);
        }

    float accPV[2][8][4];
    #pragma unroll
    for (int mt = 0; mt < 2; mt++)
        #pragma unroll
        for (int nt = 0; nt < 8; nt++)
            #pragma unroll
            for (int j = 0; j < 4; j++) accPV[mt][nt][j] = 0.f;

    const uint32_t pvb_roff = (uint32_t)((((lane >> 4) << 3) + (lane & 7)) * 128
                                         + (((lane >> 3) & 1) << 4));
    #pragma unroll
    for (int g = 0; g < 8; g++) {
        int cglob = wn * 2 + (g >> 2);
        int ksl = g & 3;
        uint32_t bbase = sb + 98304 + cglob * 8192;
        uint32_t aph[2][4];
        #pragma unroll
        for (int mt = 0; mt < 2; mt++) {
            #pragma unroll
            for (int t2 = 0; t2 < 2; t2++) {
                int tile = 2 * g + t2;
                aph[mt][2 * t2]     = packh2(accS[mt][tile][0], accS[mt][tile][1]);
                aph[mt][2 * t2 + 1] = packh2(accS[mt][tile][2], accS[mt][tile][3]);
            }
        }
        #pragma unroll
        for (int bp = 0; bp < 4; bp++) {
            uint32_t b0, b1, b2, b3;
            ldsm_x4(b0, b1, b2, b3, bbase + sw128(pvb_roff + bp * 16 * 128 + ksl * 32));
            #pragma unroll
            for (int mt = 0; mt < 2; mt++) {
                mma16816(accPV[mt][2 * bp],     aph[mt], b0, b1);
                mma16816(accPV[mt][2 * bp + 1], aph[mt], b2, b3);
            }
        }
    }

    __syncthreads();
    float* sred = (float*)ab;
    if (wn == 0) {
        #pragma unroll
        for (int mt = 0; mt < 2; mt++)
            #pragma unroll
            for (int rr = 0; rr < 2; rr++) {
                int rowl = wm * 32 + mt * 16 + rr * 8 + (lane >> 2);
                #pragma unroll
                for (int nt = 0; nt < 8; nt++) {
                    int col = nt * 8 + (lane & 3) * 2;
                    *(float2*)(sred + rowl * 66 + col) =
                        make_float2(accPV[mt][nt][2 * rr], accPV[mt][nt][2 * rr + 1]);
                }
            }
    }
    __syncthreads();
    if (wn == 1) {
        #pragma unroll
        for (int mt = 0; mt < 2; mt++)
            #pragma unroll
            for (int rr = 0; rr < 2; rr++) {
                int rowl = wm * 32 + mt * 16 + rr * 8 + (lane >> 2);
                size_t cbase = (size_t)bt * NN * CB + (size_t)(bm + rowl) * CB
                             + (size_t)head * HDD;
                #pragma unroll
                for (int nt = 0; nt < 8; nt++) {
                    int col = nt * 8 + (lane & 3) * 2;
                    float2 o = *(float2*)(sred + rowl * 66 + col);
                    float v0 = accPV[mt][nt][2 * rr]     + o.x;
                    float v1 = accPV[mt][nt][2 * rr + 1] + o.y;
                    *(__half2*)(cxh + cbase + col) = __floats2half2_rn(v0, v1);
                }
            }
    }
}

// ---------------- weight split / round ----------------
__global__ void wsplit_kernel(const float* __restrict__ w, __half* __restrict__ h,
                              __half* __restrict__ l, int n) {
    int i = blockIdx.x * 256 + threadIdx.x;
    if (i >= n) return;
    float a  = w[i];
    float hh = hfr(a);
    h[i] = __float2half_rn(hh);
    l[i] = __float2half_rn(a - hh);
}
__global__ void wround_kernel(const float* __restrict__ w, __half* __restrict__ h, int n) {
    int i = blockIdx.x * 256 + threadIdx.x;
    if (i >= n) return;
    h[i] = __float2half_rn(w[i]);
}

// ---------------- transpose + split (vw -> vwT splits) ----------------
__global__ void tsplit_kernel(const float* __restrict__ w,
                              __half* __restrict__ th, __half* __restrict__ tl) {
    __shared__ float tile[32][33];
    int bx = blockIdx.x * 32, by = blockIdx.y * 32;
    int tx = threadIdx.x & 31, ty = threadIdx.x >> 5;
    #pragma unroll
    for (int i = 0; i < 4; i++)
        tile[ty + i * 8][tx] = w[(size_t)(by + ty + i * 8) * CB + bx + tx];
    __syncthreads();
    #pragma unroll
    for (int i = 0; i < 4; i++) {
        int orow = bx + ty + i * 8;
        float a = tile[tx][ty + i * 8];
        float h = hfr(a);
        th[(size_t)orow * CB + by + tx] = __float2half_rn(h);
        tl[(size_t)orow * CB + by + tx] = __float2half_rn(a - h);
    }
}

// ---------------- bc = wv @ v_b + bv ----------------
__global__ void bc_kernel(const float* __restrict__ wv, const float* __restrict__ vb,
                          const float* __restrict__ bv, float* __restrict__ bc) {
    int d = blockIdx.x * 8 + (threadIdx.x >> 5);
    int lane = threadIdx.x & 31;
    const float* wr = wv + (size_t)d * CB;
    float s = 0.f;
    for (int k = lane * 4; k < CB; k += 128) {
        float4 w = *(const float4*)(wr + k);
        float4 v = *(const float4*)(vb + k);
        s += w.x * v.x + w.y * v.y + w.z * v.z + w.w * v.w;
    }
    #pragma unroll
    for (int off = 16; off > 0; off >>= 1) s += __shfl_xor_sync(0xffffffffu, s, off);
    if (lane == 0) bc[d] = s + bv[d];
}

// ---------------- x round + q/k splits (scale fused, packed arrays) ----------------
__global__ void qk_split_kernel(const float* __restrict__ x) {
    size_t idx = (size_t)blockIdx.x * 256 + threadIdx.x;
    size_t row = idx >> 8;
    int c4 = (int)(idx & 255) * 4;
    int srow = (int)(((row >> 12) << 8) | (row & 255));
    float4 xv = *(const float4*)(x + row * CB + c4);
    float4 qs = *(const float4*)(g_qscale + (size_t)srow * CB + c4);
    float4 ks = *(const float4*)(g_kscale + (size_t)srow * CB + c4);
    size_t base = row * CB + c4;

    float xi[4] = {xv.x, xv.y, xv.z, xv.w};
    float qi[4] = {xv.x * qs.x, xv.y * qs.y, xv.z * qs.z, xv.w * qs.w};
    float ki[4] = {xv.x * ks.x, xv.y * ks.y, xv.z * ks.z, xv.w * ks.w};

    __half xh[4], qh[4], ql[4], kh[4], kl[4];
    #pragma unroll
    for (int j = 0; j < 4; j++) {
        xh[j] = __float2half_rn(xi[j]);
        float h;
        h = hfr(qi[j]); qh[j] = __float2half_rn(h); ql[j] = __float2half_rn(qi[j] - h);
        h = hfr(ki[j]); kh[j] = __float2half_rn(h); kl[j] = __float2half_rn(ki[j] - h);
    }
    *(uint2*)(g_xh + base) = *(uint2*)xh;
    *(uint2*)(g_qkh + base)      = *(uint2*)qh;  *(uint2*)(g_qkl + base)      = *(uint2*)ql;
    *(uint2*)(g_qkh + QK + base) = *(uint2*)kh;  *(uint2*)(g_qkl + QK + base) = *(uint2*)kl;
}

// ---------------- expert sums ----------------
__global__ void expert_sum_kernel(const float* __restrict__ qe, const float* __restrict__ ke) {
    int c = blockIdx.x * 256 + threadIdx.x;
    int k = blockIdx.y;
    const float* src = blockIdx.z ? ke : qe;
    float* dst = blockIdx.z ? g_ksum : g_qsum;
    const float* p = src + (size_t)k * CB * CB + c;
    float s = 0.f;
    #pragma unroll 4
    for (int r = 0; r < CB; r++) s += p[(size_t)r * CB];
    dst[k * CB + c] = s;
}

// ---------------- dyn softmax ----------------
__global__ void dyn_kernel(const float* __restrict__ y, const float* __restrict__ dw,
                           const float* __restrict__ db) {
    int row  = blockIdx.x * 8 + (threadIdx.x >> 5);
    int lane = threadIdx.x & 31;
    const float* yr = y + (size_t)row * CB;
    float acc[KEXP];
    #pragma unroll
    for (int j = 0; j < KEXP; j++) acc[j] = 0.f;
    for (int c = lane * 4; c < CB; c += 128) {
        float4 yv = *(const float4*)(yr + c);
        #pragma unroll
        for (int j = 0; j < KEXP; j++) {
            float4 w = *(const float4*)(dw + j * CB + c);
            acc[j] += yv.x * w.x + yv.y * w.y + yv.z * w.z + yv.w * w.w;
        }
    }
    #pragma unroll
    for (int j = 0; j < KEXP; j++)
        #pragma unroll
        for (int off = 16; off > 0; off >>= 1)
            acc[j] += __shfl_xor_sync(0xffffffffu, acc[j], off);
    if (lane == 0) {
        float l[KEXP], m = -1e30f;
        #pragma unroll
        for (int j = 0; j < KEXP; j++) { l[j] = acc[j] + db[j]; m = fmaxf(m, l[j]); }
        float s = 0.f;
        #pragma unroll
        for (int j = 0; j < KEXP; j++) { l[j] = expf(l[j] - m); s += l[j]; }
        float inv = 1.f / s;
        #pragma unroll
        for (int j = 0; j < KEXP; j++) g_dyn[row * KEXP + j] = l[j] * inv;
    }
}

// ---------------- q/k scales ----------------
__global__ void scale_kernel() {
    int c  = blockIdx.x * 256 + threadIdx.x;
    int bn = blockIdx.y;
    const float* d = g_dyn + bn * KEXP;
    float qs = 0.f, ks = 0.f;
    #pragma unroll
    for (int j = 0; j < KEXP; j++) {
        float dj = d[j];
        qs += dj * g_qsum[j * CB + c];
        ks += dj * g_ksum[j * CB + c];
    }
    g_qscale[(size_t)bn * CB + c] = qs;
    g_kscale[(size_t)bn * CB + c] = ks;
}

// ---------------- attn_avg (half2 vectorized) ----------------
__global__ void attn_avg_kernel(const __half* __restrict__ AH, float* __restrict__ out2) {
    size_t e = ((size_t)blockIdx.x * 256 + threadIdx.x) * 2;
    size_t bt  = e >> 16;
    size_t rem = e & 65535;
    size_t base = bt * ((size_t)HH * NN * NN) + rem;
    float s0 = 0.f, s1 = 0.f;
    #pragma unroll
    for (int h = 0; h < HH; h++) {
        __half2 v = *(const __half2*)(AH + base + (size_t)h * NN * NN);
        float2 f = __half22float2(v);
        s0 += f.x; s1 += f.y;
    }
    *(float2*)(out2 + e) = make_float2(s0 * (1.f / HH), s1 * (1.f / HH));
}

// ---------------- LayerNorm ----------------
__device__ __forceinline__ float block_sum(float v) {
    __shared__ float sh[8];
    int lane = threadIdx.x & 31, w = threadIdx.x >> 5;
    #pragma unroll
    for (int off = 16; off > 0; off >>= 1) v += __shfl_xor_sync(0xffffffffu, v, off);
    if (lane == 0) sh[w] = v;
    __syncthreads();
    float t = (threadIdx.x < 8) ? sh[threadIdx.x] : 0.f;
    if (w == 0) {
        #pragma unroll
        for (int off = 4; off > 0; off >>= 1) t += __shfl_xor_sync(0xffffffffu, t, off);
        if (lane == 0) sh[0] = t;
    }
    __syncthreads();
    float r = sh[0];
    __syncthreads();
    return r;
}

__global__ void ln_kernel(float* __restrict__ h, const float* __restrict__ gamma,
                          const float* __restrict__ beta) {
    int row = blockIdx.x;
    float* p = h + (size_t)row * CB;
    float4 v = ((float4*)p)[threadIdx.x];
    float mu = block_sum(v.x + v.y + v.z + v.w) * (1.f / CB);
    float d0 = v.x - mu, d1 = v.y - mu, d2 = v.z - mu, d3 = v.w - mu;
    float var = block_sum(d0 * d0 + d1 * d1 + d2 * d2 + d3 * d3) * (1.f / CB);
    float inv = rsqrtf(var + EPS);
    float4 g  = ((const float4*)gamma)[threadIdx.x];
    float4 be = ((const float4*)beta)[threadIdx.x];
    float4 o;
    o.x = d0 * inv * g.x + be.x;
    o.y = d1 * inv * g.y + be.y;
    o.z = d2 * inv * g.z + be.z;
    o.w = d3 * inv * g.w + be.w;
    ((float4*)p)[threadIdx.x] = o;
}

// ---------------- launch ----------------
extern "C" void kernel_launch(void* const* d_in, const int* in_sizes, int n_in,
                              void* d_out, int out_size) {
    const float* x    = (const float*)d_in[0];
    const float* y    = (const float*)d_in[1];
    const float* q_ex = (const float*)d_in[3];
    const float* k_ex = (const float*)d_in[4];
    const float* dynw = (const float*)d_in[5];
    const float* dynb = (const float*)d_in[6];
    const float* v_w  = (const float*)d_in[7];
    const float* v_b  = (const float*)d_in[8];
    const float* in_w = (const float*)d_in[9];
    const float* in_b = (const float*)d_in[10];
    const float* o_w  = (const float*)d_in[11];
    const float* o_b  = (const float*)d_in[12];
    const float* gam  = (const float*)d_in[13];
    const float* bet  = (const float*)d_in[14];

    float* out1 = (float*)d_out;
    float* out2 = out1 + (size_t)MROWS * CB;

    #define SYM(T, v, s) T* v; cudaGetSymbolAddress((void**)&v, s);
    SYM(float, p_bc, g_bc)
    SYM(__half, p_xh, g_xh)
    SYM(__half, p_qkh, g_qkh)   SYM(__half, p_qkl, g_qkl)
    SYM(__half, p_qpkh, g_qpkh) SYM(__half, p_qpkl, g_qpkl)
    SYM(__half, p_vpth, g_vpth)
    SYM(__half, p_cxh, g_cxh)
    SYM(__half, p_ah, g_ah)
    SYM(__half, pw_qkh, w_qkh)  SYM(__half, pw_qkl, w_qkl)
    SYM(__half, pw_wvh, w_wvh)  SYM(__half, pw_wvl, w_wvl)
    SYM(__half, pw_vwth, w_vwth) SYM(__half, pw_vwtl, w_vwtl)
    SYM(__half, pw_wch, w_wch)
    SYM(__half, pw_owh, w_owh)
    #undef SYM

    const int SM_NP3 = 256 + 3 * (4 * 16384);   // 196864
    const int SM_NP1 = 256 + 3 * (2 * 16384);   //  98560
    const int SM_FL  = 256 + 131072;            // 131328
    cudaFuncSetAttribute(hmma_f16<3,0>, cudaFuncAttributeMaxDynamicSharedMemorySize, SM_NP3);
    cudaFuncSetAttribute(hmma_f16<1,0>, cudaFuncAttributeMaxDynamicSharedMemorySize, SM_NP1);
    cudaFuncSetAttribute(hmma_f16<1,2>, cudaFuncAttributeMaxDynamicSharedMemorySize, SM_NP1);
    cudaFuncSetAttribute(flash_kernel,  cudaFuncAttributeMaxDynamicSharedMemorySize, SM_FL);

    // ---- lazy one-time stream/event creation (resources only; the captured work
    //      and its dependency graph are identical on every call) ----
    static cudaStream_t s1;
    static cudaEvent_t evFork, evQK, evVPT, evFlash, evJoin;
    static bool init_done = false;
    if (!init_done) {
        cudaStreamCreateWithFlags(&s1, cudaStreamNonBlocking);
        cudaEventCreateWithFlags(&evFork,  cudaEventDisableTiming);
        cudaEventCreateWithFlags(&evQK,    cudaEventDisableTiming);
        cudaEventCreateWithFlags(&evVPT,   cudaEventDisableTiming);
        cudaEventCreateWithFlags(&evFlash, cudaEventDisableTiming);
        cudaEventCreateWithFlags(&evJoin,  cudaEventDisableTiming);
        init_done = true;
    }

    const int WNi = CB * CB;

    // ---- fork side stream ----
    cudaEventRecord(evFork, 0);
    cudaStreamWaitEvent(s1, evFork, 0);

    // ---- s1: value-chain weight prep (independent of chain A) ----
    wsplit_kernel<<<WNi / 256, 256, 0, s1>>>(in_w + 2 * WNS, pw_wvh, pw_wvl, WNi);   // wv
    wround_kernel<<<WNi / 256, 256, 0, s1>>>(o_w, pw_owh, WNi);
    tsplit_kernel<<<dim3(32, 32), 256, 0, s1>>>(v_w, pw_vwth, pw_vwtl);
    bc_kernel<<<CB / 8, 256, 0, s1>>>(in_w + 2 * WNS, v_b, in_b + 2 * CB, p_bc);
    // Wc = wv @ vw (NP3, rounded single output)
    hmma_f16<3,0><<<dim3(8, 8), 256, SM_NP3, s1>>>(
        pw_wvh, pw_wvl, pw_vwth, pw_vwtl, nullptr, pw_wch, nullptr,
        CB, CB, CB, CB, nullptr, nullptr, 0, 0);

    // ---- s0: chain A prep ----
    expert_sum_kernel<<<dim3(CB / 256, KEXP, 2), 256>>>(q_ex, k_ex);
    dyn_kernel<<<(BB * NN) / 8, 256>>>(y, dynw, dynb);
    scale_kernel<<<dim3(CB / 256, BB * NN), 256>>>();
    qk_split_kernel<<<(int)(QK / 4 / 256), 256>>>(x);
    cudaEventRecord(evQK, 0);
    wsplit_kernel<<<2 * WNi / 256, 256>>>(in_w, pw_qkh, pw_qkl, 2 * WNi);            // wq + wk

    // ---- s0: qp & kp dual-batch NP3 GEMM ----
    hmma_f16<3,0><<<dim3(8, 256, 2), 256, SM_NP3>>>(
        p_qkh, p_qkl, pw_qkh, pw_qkl, nullptr, p_qpkh, p_qpkl,
        CB, CB, CB, CB, in_b, nullptr, QK, WNS);

    // ---- s1: vpT = Wc @ x^T + bc (needs qk_split's xh) — overlaps qp/kp GEMM ----
    cudaStreamWaitEvent(s1, evQK, 0);
    hmma_f16<1,2><<<dim3(256, 8), 256, SM_NP1, s1>>>(
        pw_wch, nullptr, p_xh, nullptr, nullptr, p_vpth, nullptr,
        CB, CB, CB, CB, p_bc, nullptr, 0, 0);
    cudaEventRecord(evVPT, s1);

    // ---- s0: flash (needs qp/kp + vpT) ----
    cudaStreamWaitEvent(0, evVPT, 0);
    flash_kernel<<<dim3(2, BTT * HH), 256, SM_FL>>>(
        p_qpkh, p_qpkl, p_qpkh + QK, p_qpkl + QK, p_vpth, p_ah, p_cxh);
    cudaEventRecord(evFlash, 0);

    // ---- s1: attn_avg — overlaps out-proj + LN ----
    cudaStreamWaitEvent(s1, evFlash, 0);
    attn_avg_kernel<<<(BTT * NN * NN / 2) / 256, 256, 0, s1>>>(p_ah, out2);
    cudaEventRecord(evJoin, s1);

    // ---- s0: h = x + ctx @ out_w^T + out_b (NP1), then LayerNorm ----
    hmma_f16<1,0><<<dim3(8, 256), 256, SM_NP1>>>(
        p_cxh, nullptr, pw_owh, nullptr, out1, nullptr, nullptr,
        CB, CB, CB, CB, o_b, x, 0, 0);
    ln_kernel<<<MROWS, 256>>>(out1, gam, bet);

    // ---- join ----
    cudaStreamWaitEvent(0, evJoin, 0);
}

// round 17
// speedup vs baseline: 1.2296x; 1.0017x over previous
#include <cuda_runtime.h>
#include <cuda_fp16.h>
#include <math.h>
#include <stddef.h>
#include <stdint.h>

// ---------------- problem constants ----------------
constexpr int BB   = 8;
constexpr int TT   = 16;
constexpr int NN   = 256;
constexpr int CB   = 1024;
constexpr int HH   = 16;
constexpr int HDD  = 64;
constexpr int KEXP = 8;
constexpr int BTT  = BB * TT;          // 128
constexpr int MROWS = BTT * NN;        // 32768
constexpr float EPS = 1e-5f;
constexpr size_t QK  = (size_t)MROWS * CB;
constexpr size_t WNS = (size_t)CB * CB;

// ---------------- device scratch ----------------
__device__ __align__(128) float g_qsum[KEXP * CB];
__device__ __align__(128) float g_ksum[KEXP * CB];
__device__ __align__(128) float g_dyn[BB * NN * KEXP];
__device__ __align__(128) float g_qscale[BB * NN * CB];
__device__ __align__(128) float g_kscale[BB * NN * CB];
__device__ __align__(128) float g_bc[CB];

__device__ __align__(128) __half g_xh  [QK];
__device__ __align__(128) __half g_qkh [2 * QK];
__device__ __align__(128) __half g_qkl [2 * QK];
__device__ __align__(128) __half g_qpkh[2 * QK];
__device__ __align__(128) __half g_qpkl[2 * QK];
__device__ __align__(128) __half g_vpth[QK];
__device__ __align__(128) __half g_cxh [QK];
__device__ __align__(128) __half g_ah  [(size_t)BTT * HH * NN * NN];

__device__ __align__(128) __half w_qkh [2 * WNS];
__device__ __align__(128) __half w_qkl [2 * WNS];
__device__ __align__(128) __half w_wvh [WNS];
__device__ __align__(128) __half w_wvl [WNS];
__device__ __align__(128) __half w_vwth[WNS];
__device__ __align__(128) __half w_vwtl[WNS];
__device__ __align__(128) __half w_wch [WNS];
__device__ __align__(128) __half w_owh [WNS];

// ---------------- helpers ----------------
__device__ __forceinline__ uint32_t smem_u32(const void* p) {
    return (uint32_t)__cvta_generic_to_shared(p);
}
__device__ __forceinline__ uint32_t sw128(uint32_t o) { return o ^ ((o >> 3) & 0x70); }
__device__ __forceinline__ float hfr(float a) { return __half2float(__float2half_rn(a)); }
__device__ __forceinline__ uint32_t packh2(float a, float b) {
    __half2 t = __floats2half2_rn(a, b);
    return *(uint32_t*)&t;
}
__device__ __forceinline__ void ldsm_x4(uint32_t& r0, uint32_t& r1, uint32_t& r2, uint32_t& r3,
                                        uint32_t addr) {
    asm volatile("ldmatrix.sync.aligned.m8n8.x4.shared.b16 {%0,%1,%2,%3}, [%4];"
                 : "=r"(r0), "=r"(r1), "=r"(r2), "=r"(r3) : "r"(addr));
}
__device__ __forceinline__ void mma16816(float* d, const uint32_t* a, uint32_t b0, uint32_t b1) {
    asm volatile("mma.sync.aligned.m16n8k16.row.col.f32.f16.f16.f32 "
                 "{%0,%1,%2,%3}, {%4,%5,%6,%7}, {%8,%9}, {%0,%1,%2,%3};"
                 : "+f"(d[0]), "+f"(d[1]), "+f"(d[2]), "+f"(d[3])
                 : "r"(a[0]), "r"(a[1]), "r"(a[2]), "r"(a[3]), "r"(b0), "r"(b1));
}
__device__ __forceinline__ void cp16(uint32_t dst, const void* src) {
    asm volatile("cp.async.cg.shared.global [%0], [%1], 16;" :: "r"(dst), "l"(src) : "memory");
}
__device__ __forceinline__ void cp_commit() { asm volatile("cp.async.commit_group;" ::: "memory"); }
template<int N> __device__ __forceinline__ void cp_wait() {
    asm volatile("cp.async.wait_group %0;" :: "n"(N) : "memory");
}

// ---------------- fp16 split HMMA GEMM (plain NT), 3-stage cp.async pipeline ----------------
// NPROD=3: (A0+A1)@(B0+B1) via hh,hl,lh.  NPROD=1: A0@B0.
// OMODE 0: row-major out, bias per COL, optional resid; z-batching via az/bz.
// OMODE 2: vpT write — out[col>>8][row][col&255] half, bias per ROW.
// m-block = blockIdx.y * ymul + yoff (for half-grid pipelining).
template<int NPROD, int OMODE>
__global__ void __launch_bounds__(256, NPROD == 1 ? 2 : 1)
hmma_f16(const __half* __restrict__ A0, const __half* __restrict__ A1,
         const __half* __restrict__ B0, const __half* __restrict__ B1,
         float* __restrict__ Cf, __half* __restrict__ Ch, __half* __restrict__ Cl,
         int Kdim, int lda, int ldb, int ldc,
         const float* __restrict__ bias, const float* __restrict__ resid,
         size_t az, size_t bz, int ymul, int yoff)
{
    constexpr int NSA = (NPROD >= 2) ? 2 : 1;
    constexpr int NSB = (NPROD == 3) ? 2 : 1;
    constexpr int ATILE = 128 * 64 * 2;
    constexpr int BTILE = 128 * 64 * 2;
    constexpr int STAGE = NSA * ATILE + NSB * BTILE;

    extern __shared__ char dsm[];
    const uint32_t sraw  = smem_u32(dsm);
    const uint32_t sbase = (sraw + 127u) & ~127u;

    const int tid  = threadIdx.x;
    const int wid  = tid >> 5;
    const int lane = tid & 31;
    const int wm   = wid & 3;
    const int wn   = wid >> 2;

    if (OMODE == 0 && blockIdx.z) {
        size_t zo = blockIdx.z * az, zb = blockIdx.z * bz;
        A0 += zo; if (A1) A1 += zo;
        B0 += zb; if (B1) B1 += zb;
        if (Cf) Cf += zo;
        if (Ch) { Ch += zo; if (Cl) Cl += zo; }
        if (bias) bias += blockIdx.z * CB;
    }

    const __half* Ap[2] = {A0, A1};
    const __half* Bp[2] = {B0, B1};
    const int bm = (blockIdx.y * ymul + yoff) * 128, bn = blockIdx.x * 128;

    auto issue = [&](int s, int kt) {
        uint32_t st = sbase + s * STAGE;
        #pragma unroll
        for (int p = 0; p < NSA; p++) {
            const __half* As = Ap[p];
            #pragma unroll
            for (int r = 0; r < 4; r++) {
                int i = tid + r * 256;
                int row = i >> 3, ch = (i & 7) * 16;
                cp16(st + p * ATILE + sw128((uint32_t)(row * 128 + ch)),
                     (const char*)(As + (size_t)(bm + row) * lda + kt) + ch);
            }
        }
        #pragma unroll
        for (int p = 0; p < NSB; p++) {
            const __half* Bs = Bp[p];
            #pragma unroll
            for (int r = 0; r < 4; r++) {
                int i = tid + r * 256;
                int row = i >> 3, ch = (i & 7) * 16;
                cp16(st + NSA * ATILE + p * BTILE + sw128((uint32_t)(row * 128 + ch)),
                     (const char*)(Bs + (size_t)(bn + row) * ldb + kt) + ch);
            }
        }
        cp_commit();
    };

    float acc[2][8][4];
    #pragma unroll
    for (int mt = 0; mt < 2; mt++)
        #pragma unroll
        for (int nt = 0; nt < 8; nt++)
            #pragma unroll
            for (int j = 0; j < 4; j++) acc[mt][nt][j] = 0.f;

    const uint32_t a_roff = (uint32_t)((wm * 32 + (lane & 15)) * 128 + ((lane >> 4) << 4));
    const uint32_t b_roff = (uint32_t)((wn * 64 + ((lane >> 4) << 3) + (lane & 7)) * 128
                                       + (((lane >> 3) & 1) << 4));

    auto compute = [&](int s) {
        uint32_t st = sbase + s * STAGE;
        #pragma unroll
        for (int p = 0; p < NPROD; p++) {
            int pa, pb;
            if (NPROD == 3)      { pa = (p == 2) ? 1 : 0; pb = (p == 1) ? 1 : 0; }
            else if (NPROD == 2) { pa = p; pb = 0; }
            else                 { pa = 0; pb = 0; }
            uint32_t abp = st + pa * ATILE;
            uint32_t bbp = st + NSA * ATILE + pb * BTILE;
            #pragma unroll
            for (int ks = 0; ks < 4; ks++) {
                uint32_t a[2][4];
                #pragma unroll
                for (int mt = 0; mt < 2; mt++)
                    ldsm_x4(a[mt][0], a[mt][1], a[mt][2], a[mt][3],
                            abp + sw128(a_roff + mt * 16 * 128 + ks * 32));
                #pragma unroll
                for (int bp = 0; bp < 4; bp++) {
                    uint32_t b0, b1, b2, b3;
                    ldsm_x4(b0, b1, b2, b3, bbp + sw128(b_roff + bp * 16 * 128 + ks * 32));
                    #pragma unroll
                    for (int mt = 0; mt < 2; mt++) {
                        mma16816(acc[mt][2 * bp],     a[mt], b0, b1);
                        mma16816(acc[mt][2 * bp + 1], a[mt], b2, b3);
                    }
                }
            }
        }
    };

    const int nch = Kdim / 64;
    issue(0, 0);
    if (nch > 1) issue(1, 64);
    if (nch > 2) issue(2, 128);
    for (int t = 0; t < nch; t++) {
        int rem = nch - 1 - t;
        if (rem >= 2) cp_wait<2>();
        else if (rem == 1) cp_wait<1>();
        else cp_wait<0>();
        __syncthreads();
        compute(t % 3);
        if (t + 3 < nch) {
            __syncthreads();
            issue(t % 3, (t + 3) * 64);
        }
    }

    // ---- epilogue ----
    #pragma unroll
    for (int mt = 0; mt < 2; mt++) {
        int r0 = bm + wm * 32 + mt * 16 + (lane >> 2);
        #pragma unroll
        for (int nt = 0; nt < 8; nt++) {
            int col = bn + wn * 64 + nt * 8 + (lane & 3) * 2;
            #pragma unroll
            for (int rr = 0; rr < 2; rr++) {
                int row = r0 + rr * 8;
                float v0 = acc[mt][nt][2 * rr];
                float v1 = acc[mt][nt][2 * rr + 1];
                if (OMODE == 2) {
                    float b = bias[row];
                    v0 += b; v1 += b;
                    size_t t0 = (size_t)(col >> 8) * (CB * NN) + (size_t)row * NN + (col & 255);
                    *(__half2*)(Ch + t0) = __floats2half2_rn(v0, v1);
                } else {
                    if (bias)  { v0 += bias[col]; v1 += bias[col + 1]; }
                    if (resid) {
                        const float* rp = resid + (size_t)row * ldc + col;
                        v0 += rp[0]; v1 += rp[1];
                    }
                    size_t base = (size_t)row * ldc + col;
                    if (Cf) *(float2*)(Cf + base) = make_float2(v0, v1);
                    if (Ch && Cl) {
                        float h0 = hfr(v0), h1 = hfr(v1);
                        *(__half2*)(Ch + base) = __floats2half2_rn(h0, h1);
                        *(__half2*)(Cl + base) = __floats2half2_rn(v0 - h0, v1 - h1);
                    } else if (Ch) {
                        *(__half2*)(Ch + base) = __floats2half2_rn(v0, v1);
                    }
                }
            }
        }
    }
}

// ---------------- flash attention (per-half: bm passed as arg; 1-D grid over BT*H) ----------------
__global__ void __launch_bounds__(256)
flash_kernel(const __half* __restrict__ qph, const __half* __restrict__ qpl,
             const __half* __restrict__ kph, const __half* __restrict__ kpl,
             const __half* __restrict__ vpt,
             __half* __restrict__ AH, __half* __restrict__ cxh, int bm)
{
    extern __shared__ char dsm[];
    const uint32_t sraw = smem_u32(dsm);
    const uint32_t sb   = (sraw + 127u) & ~127u;
    char* const ab      = dsm + (sb - sraw);

    const int tid = threadIdx.x, wid = tid >> 5, lane = tid & 31;
    const int wm = wid & 3, wn = wid >> 2;
    const int z = blockIdx.x;
    const int bt = z >> 4, head = z & 15;

    const size_t qoff = (size_t)bt * NN * CB + (size_t)head * HDD;
    const size_t voff = (size_t)bt * CB * NN + (size_t)head * HDD * NN;

    {
        const __half* qs[2] = {qph, qpl};
        #pragma unroll
        for (int p = 0; p < 2; p++)
            #pragma unroll
            for (int r = 0; r < 4; r++) {
                int i = tid + r * 256;
                int row = i >> 3, ch = (i & 7) * 16;
                cp16(sb + p * 16384 + sw128((uint32_t)(row * 128 + ch)),
                     (const char*)(qs[p] + qoff + (size_t)(bm + row) * CB) + ch);
            }
        const __half* ks[2] = {kph, kpl};
        #pragma unroll
        for (int p = 0; p < 2; p++)
            #pragma unroll
            for (int r = 0; r < 8; r++) {
                int i = tid + r * 256;
                int row = i >> 3, ch = (i & 7) * 16;
                cp16(sb + 32768 + p * 32768 + sw128((uint32_t)(row * 128 + ch)),
                     (const char*)(ks[p] + qoff + (size_t)row * CB) + ch);
            }
        #pragma unroll
        for (int c = 0; c < 4; c++)
            #pragma unroll
            for (int r = 0; r < 2; r++) {
                int i = tid + r * 256;
                int row = i >> 3, ch = (i & 7) * 16;
                cp16(sb + 98304 + c * 8192 + sw128((uint32_t)(row * 128 + ch)),
                     (const char*)(vpt + voff + (size_t)row * NN + c * 64) + ch);
            }
        cp_commit();
        cp_wait<0>();
        __syncthreads();
    }

    float accS[2][16][4];
    #pragma unroll
    for (int mt = 0; mt < 2; mt++)
        #pragma unroll
        for (int nt = 0; nt < 16; nt++)
            #pragma unroll
            for (int j = 0; j < 4; j++) accS[mt][nt][j] = 0.f;

    const uint32_t a_roff = (uint32_t)((wm * 32 + (lane & 15)) * 128 + ((lane >> 4) << 4));
    const uint32_t b_roff = (uint32_t)((wn * 128 + ((lane >> 4) << 3) + (lane & 7)) * 128
                                       + (((lane >> 3) & 1) << 4));
    #pragma unroll
    for (int p = 0; p < 3; p++) {
        uint32_t abp = sb + ((p == 1) ? 16384 : 0);
        uint32_t bbp = sb + 32768 + ((p == 2) ? 32768 : 0);
        #pragma unroll
        for (int ks = 0; ks < 4; ks++) {
            uint32_t a[2][4];
            #pragma unroll
            for (int mt = 0; mt < 2; mt++)
                ldsm_x4(a[mt][0], a[mt][1], a[mt][2], a[mt][3],
                        abp + sw128(a_roff + mt * 16 * 128 + ks * 32));
            #pragma unroll
            for (int bp = 0; bp < 8; bp++) {
                uint32_t b0, b1, b2, b3;
                ldsm_x4(b0, b1, b2, b3, bbp + sw128(b_roff + bp * 16 * 128 + ks * 32));
                #pragma unroll
                for (int mt = 0; mt < 2; mt++) {
                    mma16816(accS[mt][2 * bp],     a[mt], b0, b1);
                    mma16816(accS[mt][2 * bp + 1], a[mt], b2, b3);
                }
            }
        }
    }
    __syncthreads();

    float* red = (float*)ab;
    float rmax[2][2];
    #pragma unroll
    for (int mt = 0; mt < 2; mt++)
        #pragma unroll
        for (int rr = 0; rr < 2; rr++) {
            float m = -1e30f;
            #pragma unroll
            for (int nt = 0; nt < 16; nt++)
                m = fmaxf(m, fmaxf(accS[mt][nt][2 * rr], accS[mt][nt][2 * rr + 1]));
            m = fmaxf(m, __shfl_xor_sync(0xffffffffu, m, 1));
            m = fmaxf(m, __shfl_xor_sync(0xffffffffu, m, 2));
            int rowl = wm * 32 + mt * 16 + rr * 8 + (lane >> 2);
            if ((lane & 3) == 0) red[wn * 128 + rowl] = m;
        }
    __syncthreads();
    #pragma unroll
    for (int mt = 0; mt < 2; mt++)
        #pragma unroll
        for (int rr = 0; rr < 2; rr++) {
            int rowl = wm * 32 + mt * 16 + rr * 8 + (lane >> 2);
            rmax[mt][rr] = fmaxf(red[rowl], red[128 + rowl]);
        }
    __syncthreads();
    #pragma unroll
    for (int mt = 0; mt < 2; mt++)
        #pragma unroll
        for (int rr = 0; rr < 2; rr++) {
            float m = rmax[mt][rr], s = 0.f;
            #pragma unroll
            for (int nt = 0; nt < 16; nt++) {
                float e0 = __expf((accS[mt][nt][2 * rr]     - m) * 0.125f);
                float e1 = __expf((accS[mt][nt][2 * rr + 1] - m) * 0.125f);
                accS[mt][nt][2 * rr]     = e0;
                accS[mt][nt][2 * rr + 1] = e1;
                s += e0 + e1;
            }
            s += __shfl_xor_sync(0xffffffffu, s, 1);
            s += __shfl_xor_sync(0xffffffffu, s, 2);
            int rowl = wm * 32 + mt * 16 + rr * 8 + (lane >> 2);
            if ((lane & 3) == 0) red[wn * 128 + rowl] = s;
        }
    __syncthreads();
    #pragma unroll
    for (int mt = 0; mt < 2; mt++)
        #pragma unroll
        for (int rr = 0; rr < 2; rr++) {
            int rowl = wm * 32 + mt * 16 + rr * 8 + (lane >> 2);
            float inv = 1.f / (red[rowl] + red[128 + rowl]);
            #pragma unroll
            for (int nt = 0; nt < 16; nt++) {
                accS[mt][nt][2 * rr]     *= inv;
                accS[mt][nt][2 * rr + 1] *= inv;
            }
        }

    #pragma unroll
    for (int mt = 0; mt < 2; mt++)
        #pragma unroll
        for (int rr = 0; rr < 2; rr++) {
            int rowl = wm * 32 + mt * 16 + rr * 8 + (lane >> 2);
            size_t rbase = (size_t)z * (NN * NN) + (size_t)(bm + rowl) * NN
                         + wn * 128 + (lane & 3) * 2;
            #pragma unroll
            for (int nt = 0; nt < 16; nt++)
                *(__half2*)(AH + rbase + nt * 8) =
                    __floats2half2_rn(accS[mt][nt][2 * rr], accS[mt][nt][2 * rr + 1]);
        }

    float accPV[2][8][4];
    #pragma unroll
    for (int mt = 0; mt < 2; mt++)
        #pragma unroll
        for (int nt = 0; nt < 8; nt++)
            #pragma unroll
            for (int j = 0; j < 4; j++) accPV[mt][nt][j] = 0.f;

    const uint32_t pvb_roff = (uint32_t)((((lane >> 4) << 3) + (lane & 7)) * 128
                                         + (((lane >> 3) & 1) << 4));
    #pragma unroll
    for (int g = 0; g < 8; g++) {
        int cglob = wn * 2 + (g >> 2);
        int ksl = g & 3;
        uint32_t bbase = sb + 98304 + cglob * 8192;
        uint32_t aph[2][4];
        #pragma unroll
        for (int mt = 0; mt < 2; mt++) {
            #pragma unroll
            for (int t2 = 0; t2 < 2; t2++) {
                int tile = 2 * g + t2;
                aph[mt][2 * t2]     = packh2(accS[mt][tile][0], accS[mt][tile][1]);
                aph[mt][2 * t2 + 1] = packh2(accS[mt][tile][2], accS[mt][tile][3]);
            }
        }
        #pragma unroll
        for (int bp = 0; bp < 4; bp++) {
            uint32_t b0, b1, b2, b3;
            ldsm_x4(b0, b1, b2, b3, bbase + sw128(pvb_roff + bp * 16 * 128 + ksl * 32));
            #pragma unroll
            for (int mt = 0; mt < 2; mt++) {
                mma16816(accPV[mt][2 * bp],     aph[mt], b0, b1);
                mma16816(accPV[mt][2 * bp + 1], aph[mt], b2, b3);
            }
        }
    }

    __syncthreads();
    float* sred = (float*)ab;
    if (wn == 0) {
        #pragma unroll
        for (int mt = 0; mt < 2; mt++)
            #pragma unroll
            for (int rr = 0; rr < 2; rr++) {
                int rowl = wm * 32 + mt * 16 + rr * 8 + (lane >> 2);
                #pragma unroll
                for (int nt = 0; nt < 8; nt++) {
                    int col = nt * 8 + (lane & 3) * 2;
                    *(float2*)(sred + rowl * 66 + col) =
                        make_float2(accPV[mt][nt][2 * rr], accPV[mt][nt][2 * rr + 1]);
                }
            }
    }
    __syncthreads();
    if (wn == 1) {
        #pragma unroll
        for (int mt = 0; mt < 2; mt++)
            #pragma unroll
            for (int rr = 0; rr < 2; rr++) {
                int rowl = wm * 32 + mt * 16 + rr * 8 + (lane >> 2);
                size_t cbase = (size_t)bt * NN * CB + (size_t)(bm + rowl) * CB
                             + (size_t)head * HDD;
                #pragma unroll
                for (int nt = 0; nt < 8; nt++) {
                    int col = nt * 8 + (lane & 3) * 2;
                    float2 o = *(float2*)(sred + rowl * 66 + col);
                    float v0 = accPV[mt][nt][2 * rr]     + o.x;
                    float v1 = accPV[mt][nt][2 * rr + 1] + o.y;
                    *(__half2*)(cxh + cbase + col) = __floats2half2_rn(v0, v1);
                }
            }
    }
}

// ---------------- weight split / round ----------------
__global__ void wsplit_kernel(const float* __restrict__ w, __half* __restrict__ h,
                              __half* __restrict__ l, int n) {
    int i = blockIdx.x * 256 + threadIdx.x;
    if (i >= n) return;
    float a  = w[i];
    float hh = hfr(a);
    h[i] = __float2half_rn(hh);
    l[i] = __float2half_rn(a - hh);
}
__global__ void wround_kernel(const float* __restrict__ w, __half* __restrict__ h, int n) {
    int i = blockIdx.x * 256 + threadIdx.x;
    if (i >= n) return;
    h[i] = __float2half_rn(w[i]);
}

// ---------------- transpose + split (vw -> vwT splits) ----------------
__global__ void tsplit_kernel(const float* __restrict__ w,
                              __half* __restrict__ th, __half* __restrict__ tl) {
    __shared__ float tile[32][33];
    int bx = blockIdx.x * 32, by = blockIdx.y * 32;
    int tx = threadIdx.x & 31, ty = threadIdx.x >> 5;
    #pragma unroll
    for (int i = 0; i < 4; i++)
        tile[ty + i * 8][tx] = w[(size_t)(by + ty + i * 8) * CB + bx + tx];
    __syncthreads();
    #pragma unroll
    for (int i = 0; i < 4; i++) {
        int orow = bx + ty + i * 8;
        float a = tile[tx][ty + i * 8];
        float h = hfr(a);
        th[(size_t)orow * CB + by + tx] = __float2half_rn(h);
        tl[(size_t)orow * CB + by + tx] = __float2half_rn(a - h);
    }
}

// ---------------- bc = wv @ v_b + bv ----------------
__global__ void bc_kernel(const float* __restrict__ wv, const float* __restrict__ vb,
                          const float* __restrict__ bv, float* __restrict__ bc) {
    int d = blockIdx.x * 8 + (threadIdx.x >> 5);
    int lane = threadIdx.x & 31;
    const float* wr = wv + (size_t)d * CB;
    float s = 0.f;
    for (int k = lane * 4; k < CB; k += 128) {
        float4 w = *(const float4*)(wr + k);
        float4 v = *(const float4*)(vb + k);
        s += w.x * v.x + w.y * v.y + w.z * v.z + w.w * v.w;
    }
    #pragma unroll
    for (int off = 16; off > 0; off >>= 1) s += __shfl_xor_sync(0xffffffffu, s, off);
    if (lane == 0) bc[d] = s + bv[d];
}

// ---------------- x round + q/k splits (scale fused, packed arrays) ----------------
__global__ void qk_split_kernel(const float* __restrict__ x) {
    size_t idx = (size_t)blockIdx.x * 256 + threadIdx.x;
    size_t row = idx >> 8;
    int c4 = (int)(idx & 255) * 4;
    int srow = (int)(((row >> 12) << 8) | (row & 255));
    float4 xv = *(const float4*)(x + row * CB + c4);
    float4 qs = *(const float4*)(g_qscale + (size_t)srow * CB + c4);
    float4 ks = *(const float4*)(g_kscale + (size_t)srow * CB + c4);
    size_t base = row * CB + c4;

    float xi[4] = {xv.x, xv.y, xv.z, xv.w};
    float qi[4] = {xv.x * qs.x, xv.y * qs.y, xv.z * qs.z, xv.w * qs.w};
    float ki[4] = {xv.x * ks.x, xv.y * ks.y, xv.z * ks.z, xv.w * ks.w};

    __half xh[4], qh[4], ql[4], kh[4], kl[4];
    #pragma unroll
    for (int j = 0; j < 4; j++) {
        xh[j] = __float2half_rn(xi[j]);
        float h;
        h = hfr(qi[j]); qh[j] = __float2half_rn(h); ql[j] = __float2half_rn(qi[j] - h);
        h = hfr(ki[j]); kh[j] = __float2half_rn(h); kl[j] = __float2half_rn(ki[j] - h);
    }
    *(uint2*)(g_xh + base) = *(uint2*)xh;
    *(uint2*)(g_qkh + base)      = *(uint2*)qh;  *(uint2*)(g_qkl + base)      = *(uint2*)ql;
    *(uint2*)(g_qkh + QK + base) = *(uint2*)kh;  *(uint2*)(g_qkl + QK + base) = *(uint2*)kl;
}

// ---------------- expert sums ----------------
__global__ void expert_sum_kernel(const float* __restrict__ qe, const float* __restrict__ ke) {
    int c = blockIdx.x * 256 + threadIdx.x;
    int k = blockIdx.y;
    const float* src = blockIdx.z ? ke : qe;
    float* dst = blockIdx.z ? g_ksum : g_qsum;
    const float* p = src + (size_t)k * CB * CB + c;
    float s = 0.f;
    #pragma unroll 4
    for (int r = 0; r < CB; r++) s += p[(size_t)r * CB];
    dst[k * CB + c] = s;
}

// ---------------- dyn softmax ----------------
__global__ void dyn_kernel(const float* __restrict__ y, const float* __restrict__ dw,
                           const float* __restrict__ db) {
    int row  = blockIdx.x * 8 + (threadIdx.x >> 5);
    int lane = threadIdx.x & 31;
    const float* yr = y + (size_t)row * CB;
    float acc[KEXP];
    #pragma unroll
    for (int j = 0; j < KEXP; j++) acc[j] = 0.f;
    for (int c = lane * 4; c < CB; c += 128) {
        float4 yv = *(const float4*)(yr + c);
        #pragma unroll
        for (int j = 0; j < KEXP; j++) {
            float4 w = *(const float4*)(dw + j * CB + c);
            acc[j] += yv.x * w.x + yv.y * w.y + yv.z * w.z + yv.w * w.w;
        }
    }
    #pragma unroll
    for (int j = 0; j < KEXP; j++)
        #pragma unroll
        for (int off = 16; off > 0; off >>= 1)
            acc[j] += __shfl_xor_sync(0xffffffffu, acc[j], off);
    if (lane == 0) {
        float l[KEXP], m = -1e30f;
        #pragma unroll
        for (int j = 0; j < KEXP; j++) { l[j] = acc[j] + db[j]; m = fmaxf(m, l[j]); }
        float s = 0.f;
        #pragma unroll
        for (int j = 0; j < KEXP; j++) { l[j] = expf(l[j] - m); s += l[j]; }
        float inv = 1.f / s;
        #pragma unroll
        for (int j = 0; j < KEXP; j++) g_dyn[row * KEXP + j] = l[j] * inv;
    }
}

// ---------------- q/k scales ----------------
__global__ void scale_kernel() {
    int c  = blockIdx.x * 256 + threadIdx.x;
    int bn = blockIdx.y;
    const float* d = g_dyn + bn * KEXP;
    float qs = 0.f, ks = 0.f;
    #pragma unroll
    for (int j = 0; j < KEXP; j++) {
        float dj = d[j];
        qs += dj * g_qsum[j * CB + c];
        ks += dj * g_ksum[j * CB + c];
    }
    g_qscale[(size_t)bn * CB + c] = qs;
    g_kscale[(size_t)bn * CB + c] = ks;
}

// ---------------- attn_avg (half2, per m-half: yoff = half*32768) ----------------
__global__ void attn_avg_kernel(const __half* __restrict__ AH, float* __restrict__ out2,
                                size_t yoff) {
    size_t e = ((size_t)blockIdx.x * 256 + threadIdx.x) * 2;   // within half per bt: 32768 elems
    size_t bt  = e >> 15;
    size_t rem = e & 32767;
    size_t obase = bt * 65536 + yoff + rem;
    size_t abase = bt * ((size_t)HH * 65536) + yoff + rem;
    float s0 = 0.f, s1 = 0.f;
    #pragma unroll
    for (int h = 0; h < HH; h++) {
        __half2 v = *(const __half2*)(AH + abase + (size_t)h * 65536);
        float2 f = __half22float2(v);
        s0 += f.x; s1 += f.y;
    }
    *(float2*)(out2 + obase) = make_float2(s0 * (1.f / HH), s1 * (1.f / HH));
}

// ---------------- LayerNorm (per m-half: yoff = half*128) ----------------
__device__ __forceinline__ float block_sum(float v) {
    __shared__ float sh[8];
    int lane = threadIdx.x & 31, w = threadIdx.x >> 5;
    #pragma unroll
    for (int off = 16; off > 0; off >>= 1) v += __shfl_xor_sync(0xffffffffu, v, off);
    if (lane == 0) sh[w] = v;
    __syncthreads();
    float t = (threadIdx.x < 8) ? sh[threadIdx.x] : 0.f;
    if (w == 0) {
        #pragma unroll
        for (int off = 4; off > 0; off >>= 1) t += __shfl_xor_sync(0xffffffffu, t, off);
        if (lane == 0) sh[0] = t;
    }
    __syncthreads();
    float r = sh[0];
    __syncthreads();
    return r;
}

__global__ void ln_kernel(float* __restrict__ h, const float* __restrict__ gamma,
                          const float* __restrict__ beta, int yoff) {
    int row = ((blockIdx.x >> 7) << 8) + yoff + (blockIdx.x & 127);
    float* p = h + (size_t)row * CB;
    float4 v = ((float4*)p)[threadIdx.x];
    float mu = block_sum(v.x + v.y + v.z + v.w) * (1.f / CB);
    float d0 = v.x - mu, d1 = v.y - mu, d2 = v.z - mu, d3 = v.w - mu;
    float var = block_sum(d0 * d0 + d1 * d1 + d2 * d2 + d3 * d3) * (1.f / CB);
    float inv = rsqrtf(var + EPS);
    float4 g  = ((const float4*)gamma)[threadIdx.x];
    float4 be = ((const float4*)beta)[threadIdx.x];
    float4 o;
    o.x = d0 * inv * g.x + be.x;
    o.y = d1 * inv * g.y + be.y;
    o.z = d2 * inv * g.z + be.z;
    o.w = d3 * inv * g.w + be.w;
    ((float4*)p)[threadIdx.x] = o;
}

// ---------------- launch ----------------
extern "C" void kernel_launch(void* const* d_in, const int* in_sizes, int n_in,
                              void* d_out, int out_size) {
    const float* x    = (const float*)d_in[0];
    const float* y    = (const float*)d_in[1];
    const float* q_ex = (const float*)d_in[3];
    const float* k_ex = (const float*)d_in[4];
    const float* dynw = (const float*)d_in[5];
    const float* dynb = (const float*)d_in[6];
    const float* v_w  = (const float*)d_in[7];
    const float* v_b  = (const float*)d_in[8];
    const float* in_w = (const float*)d_in[9];
    const float* in_b = (const float*)d_in[10];
    const float* o_w  = (const float*)d_in[11];
    const float* o_b  = (const float*)d_in[12];
    const float* gam  = (const float*)d_in[13];
    const float* bet  = (const float*)d_in[14];

    float* out1 = (float*)d_out;
    float* out2 = out1 + (size_t)MROWS * CB;

    #define SYM(T, v, s) T* v; cudaGetSymbolAddress((void**)&v, s);
    SYM(float, p_bc, g_bc)
    SYM(__half, p_xh, g_xh)
    SYM(__half, p_qkh, g_qkh)   SYM(__half, p_qkl, g_qkl)
    SYM(__half, p_qpkh, g_qpkh) SYM(__half, p_qpkl, g_qpkl)
    SYM(__half, p_vpth, g_vpth)
    SYM(__half, p_cxh, g_cxh)
    SYM(__half, p_ah, g_ah)
    SYM(__half, pw_qkh, w_qkh)  SYM(__half, pw_qkl, w_qkl)
    SYM(__half, pw_wvh, w_wvh)  SYM(__half, pw_wvl, w_wvl)
    SYM(__half, pw_vwth, w_vwth) SYM(__half, pw_vwtl, w_vwtl)
    SYM(__half, pw_wch, w_wch)
    SYM(__half, pw_owh, w_owh)
    #undef SYM

    const int SM_NP3 = 256 + 3 * (4 * 16384);   // 196864
    const int SM_NP1 = 256 + 3 * (2 * 16384);   //  98560
    const int SM_FL  = 256 + 131072;            // 131328
    cudaFuncSetAttribute(hmma_f16<3,0>, cudaFuncAttributeMaxDynamicSharedMemorySize, SM_NP3);
    cudaFuncSetAttribute(hmma_f16<1,0>, cudaFuncAttributeMaxDynamicSharedMemorySize, SM_NP1);
    cudaFuncSetAttribute(hmma_f16<1,2>, cudaFuncAttributeMaxDynamicSharedMemorySize, SM_NP1);
    cudaFuncSetAttribute(flash_kernel,  cudaFuncAttributeMaxDynamicSharedMemorySize, SM_FL);

    // ---- lazy one-time stream/event creation ----
    static cudaStream_t s1, s2;
    static cudaEvent_t evFork, evQK, evW, evVPT, evF0, evF1, evJoin;
    static bool init_done = false;
    if (!init_done) {
        cudaStreamCreateWithFlags(&s1, cudaStreamNonBlocking);
        cudaStreamCreateWithFlags(&s2, cudaStreamNonBlocking);
        cudaEventCreateWithFlags(&evFork, cudaEventDisableTiming);
        cudaEventCreateWithFlags(&evQK,   cudaEventDisableTiming);
        cudaEventCreateWithFlags(&evW,    cudaEventDisableTiming);
        cudaEventCreateWithFlags(&evVPT,  cudaEventDisableTiming);
        cudaEventCreateWithFlags(&evF0,   cudaEventDisableTiming);
        cudaEventCreateWithFlags(&evF1,   cudaEventDisableTiming);
        cudaEventCreateWithFlags(&evJoin, cudaEventDisableTiming);
        init_done = true;
    }

    const int WNi = CB * CB;

    // ---- fork ----
    cudaEventRecord(evFork, 0);
    cudaStreamWaitEvent(s1, evFork, 0);
    cudaStreamWaitEvent(s2, evFork, 0);

    // ---- s2: wq/wk split + ow round (independent of everything else) ----
    wsplit_kernel<<<2 * WNi / 256, 256, 0, s2>>>(in_w, pw_qkh, pw_qkl, 2 * WNi);
    wround_kernel<<<WNi / 256, 256, 0, s2>>>(o_w, pw_owh, WNi);
    cudaEventRecord(evW, s2);

    // ---- s1: value-chain weight prep + Wc GEMM ----
    wsplit_kernel<<<WNi / 256, 256, 0, s1>>>(in_w + 2 * WNS, pw_wvh, pw_wvl, WNi);
    tsplit_kernel<<<dim3(32, 32), 256, 0, s1>>>(v_w, pw_vwth, pw_vwtl);
    bc_kernel<<<CB / 8, 256, 0, s1>>>(in_w + 2 * WNS, v_b, in_b + 2 * CB, p_bc);
    hmma_f16<3,0><<<dim3(8, 8), 256, SM_NP3, s1>>>(
        pw_wvh, pw_wvl, pw_vwth, pw_vwtl, nullptr, pw_wch, nullptr,
        CB, CB, CB, CB, nullptr, nullptr, 0, 0, 1, 0);

    // ---- s0: chain A prep ----
    expert_sum_kernel<<<dim3(CB / 256, KEXP, 2), 256>>>(q_ex, k_ex);
    dyn_kernel<<<(BB * NN) / 8, 256>>>(y, dynw, dynb);
    scale_kernel<<<dim3(CB / 256, BB * NN), 256>>>();
    qk_split_kernel<<<(int)(QK / 4 / 256), 256>>>(x);
    cudaEventRecord(evQK, 0);

    // ---- s0: qp & kp dual-batch NP3 GEMM (needs wq/wk from s2) ----
    cudaStreamWaitEvent(0, evW, 0);
    hmma_f16<3,0><<<dim3(8, 256, 2), 256, SM_NP3>>>(
        p_qkh, p_qkl, pw_qkh, pw_qkl, nullptr, p_qpkh, p_qpkl,
        CB, CB, CB, CB, in_b, nullptr, QK, WNS, 1, 0);

    // ---- s1: vpT = Wc @ x^T + bc (needs qk_split) — overlaps qp/kp GEMM ----
    cudaStreamWaitEvent(s1, evQK, 0);
    hmma_f16<1,2><<<dim3(256, 8), 256, SM_NP1, s1>>>(
        pw_wch, nullptr, p_xh, nullptr, nullptr, p_vpth, nullptr,
        CB, CB, CB, CB, p_bc, nullptr, 0, 0, 1, 0);
    cudaEventRecord(evVPT, s1);

    // ---- s0: flash in two m-halves ----
    cudaStreamWaitEvent(0, evVPT, 0);
    flash_kernel<<<BTT * HH, 256, SM_FL>>>(
        p_qpkh, p_qpkl, p_qpkh + QK, p_qpkl + QK, p_vpth, p_ah, p_cxh, 0);
    cudaEventRecord(evF0, 0);
    flash_kernel<<<BTT * HH, 256, SM_FL>>>(
        p_qpkh, p_qpkl, p_qpkh + QK, p_qpkl + QK, p_vpth, p_ah, p_cxh, 128);
    cudaEventRecord(evF1, 0);

    // ---- s1: half-A tail (overlaps flashB on s0) ----
    cudaStreamWaitEvent(s1, evF0, 0);
    cudaStreamWaitEvent(s1, evW, 0);
    hmma_f16<1,0><<<dim3(8, 128), 256, SM_NP1, s1>>>(
        p_cxh, nullptr, pw_owh, nullptr, out1, nullptr, nullptr,
        CB, CB, CB, CB, o_b, x, 0, 0, 2, 0);
    ln_kernel<<<MROWS / 2, 256, 0, s1>>>(out1, gam, bet, 0);
    attn_avg_kernel<<<(BTT * 32768 / 2) / 256, 256, 0, s1>>>(p_ah, out2, 0);
    cudaStreamWaitEvent(s1, evF1, 0);
    attn_avg_kernel<<<(BTT * 32768 / 2) / 256, 256, 0, s1>>>(p_ah, out2, 32768);
    cudaEventRecord(evJoin, s1);

    // ---- s0: half-B tail ----
    hmma_f16<1,0><<<dim3(8, 128), 256, SM_NP1>>>(
        p_cxh, nullptr, pw_owh, nullptr, out1, nullptr, nullptr,
        CB, CB, CB, CB, o_b, x, 0, 0, 2, 1);
    ln_kernel<<<MROWS / 2, 256>>>(out1, gam, bet, 128);

    // ---- join ----
    cudaStreamWaitEvent(0, evJoin, 0);
}